// round 3
// baseline (speedup 1.0000x reference)
#include <cuda_runtime.h>
#include <cuda_bf16.h>
#include <math.h>

#define NMAX 50000
#define EMAX 800000
#define DH   256
#define DIN  128
#define NG   64

// ---------------- device scratch (no allocations allowed) ----------------
__device__ float g_bufA[(size_t)NMAX * DH];
__device__ float g_bufB[(size_t)NMAX * DH];
__device__ float g_agg [(size_t)NMAX * DH];
__device__ int   g_rowptr[NMAX + 1];
__device__ int   g_cnt [NMAX];
__device__ int   g_cnt2[NMAX];
__device__ int   g_col [EMAX];
__device__ float g_colsum[DIN];
__device__ float g_gcnt[NG];

// ---------------- zero scratch + output accumulators ----------------
__global__ void k_zero(float* __restrict__ out, int n) {
    int i = blockIdx.x * blockDim.x + threadIdx.x;
    if (i < n)          { g_cnt[i] = 0; g_cnt2[i] = 0; }
    if (i < NG * DH)    out[i] = 0.f;
    if (i < DIN)        g_colsum[i] = 0.f;
    if (i < NG)         g_gcnt[i] = 0.f;
}

// ---------------- CSR build: histogram, scan, fill ----------------
__global__ void k_hist(const int* __restrict__ dst, int E) {
    int e = blockIdx.x * blockDim.x + threadIdx.x;
    if (e < E) atomicAdd(&g_cnt[dst[e]], 1);
}

__global__ void k_scan(int n) {
    __shared__ int sh[1024];
    int t = threadIdx.x;
    int C = (n + 1023) >> 10;
    int b = t * C;
    int e = min(n, b + C);
    int s = 0;
    for (int i = b; i < e; ++i) s += g_cnt[i];
    sh[t] = s;
    __syncthreads();
    for (int off = 1; off < 1024; off <<= 1) {
        int v = (t >= off) ? sh[t - off] : 0;
        __syncthreads();
        sh[t] += v;
        __syncthreads();
    }
    int run = (t == 0) ? 0 : sh[t - 1];
    for (int i = b; i < e; ++i) { g_rowptr[i] = run; run += g_cnt[i]; }
    if (t == 1023) g_rowptr[n] = sh[1023];
}

__global__ void k_fill(const int* __restrict__ src,
                       const int* __restrict__ dst, int E) {
    int e = blockIdx.x * blockDim.x + threadIdx.x;
    if (e < E) {
        int d = dst[e];
        int pos = g_rowptr[d] + atomicAdd(&g_cnt2[d], 1);
        g_col[pos] = src[e];
    }
}

// ---------------- handcrafted: column sums of x ----------------
__global__ void k_colsum(const float* __restrict__ x, int n) {
    int t = threadIdx.x;  // 128 threads = DIN channels
    float acc = 0.f;
    for (int r = blockIdx.x; r < n; r += gridDim.x)
        acc += x[(size_t)r * DIN + t];
    atomicAdd(&g_colsum[t], acc);
}

__global__ void k_hand(float* __restrict__ out) {
    __shared__ float sh[DIN];
    int t = threadIdx.x;
    float v = g_colsum[t];
    sh[t] = v;
    __syncthreads();
    for (int o = 64; o > 0; o >>= 1) {
        if (t < o) sh[t] += sh[t + o];
        __syncthreads();
    }
    float total = sh[0];
    out[NG * DH + t] = v / total;
    if (t == 0) out[NG * DH + DIN] = logf(total);
}

// ---------------- aggregation: warp per dst node, CSR float4 gather ----------------
// SRC: 0 = external x (D=128), 1 = g_bufA, 2 = g_bufB (D=256)
template<int D, int SRC>
__global__ void k_agg(const float* __restrict__ xin, int n) {
    const float* __restrict__ h =
        (SRC == 0) ? xin : (SRC == 1 ? (const float*)g_bufA : (const float*)g_bufB);
    int warp = blockIdx.x * 8 + (threadIdx.x >> 5);
    int lane = threadIdx.x & 31;
    if (warp >= n) return;
    int s = g_rowptr[warp];
    int e = g_rowptr[warp + 1];
    float4 a0 = make_float4(0.f, 0.f, 0.f, 0.f);
    float4 a1 = make_float4(0.f, 0.f, 0.f, 0.f);
    int i = s;
    for (; i + 2 <= e; i += 2) {
        int u = g_col[i], v = g_col[i + 1];
        const float4* pu = (const float4*)(h + (size_t)u * D);
        const float4* pv = (const float4*)(h + (size_t)v * D);
        float4 x0 = pu[lane];
        float4 y0 = pv[lane];
        a0.x += x0.x + y0.x; a0.y += x0.y + y0.y;
        a0.z += x0.z + y0.z; a0.w += x0.w + y0.w;
        if (D == 256) {
            float4 x1 = pu[lane + 32];
            float4 y1 = pv[lane + 32];
            a1.x += x1.x + y1.x; a1.y += x1.y + y1.y;
            a1.z += x1.z + y1.z; a1.w += x1.w + y1.w;
        }
    }
    if (i < e) {
        int u = g_col[i];
        const float4* pu = (const float4*)(h + (size_t)u * D);
        float4 x0 = pu[lane];
        a0.x += x0.x; a0.y += x0.y; a0.z += x0.z; a0.w += x0.w;
        if (D == 256) {
            float4 x1 = pu[lane + 32];
            a1.x += x1.x; a1.y += x1.y; a1.z += x1.z; a1.w += x1.w;
        }
    }
    float4* o = (float4*)(g_agg + (size_t)warp * D);
    o[lane] = a0;
    if (D == 256) o[lane + 32] = a1;
}

// ---------------- fused dual GEMM: out = relu(A1@B1 + A2@B2 + bias) ----------------
// BM=BN=64, BK=16, 256 threads, 4x4 micro-tile per thread.
// LAYER wires A1/A2/out to device globals at compile time.
//   LAYER 1: A1=g_agg, A2=x (K=128),    out=g_bufA
//   LAYER 2: A1=g_agg, A2=g_bufA (256), out=g_bufB
//   LAYER 3: A1=g_agg, A2=g_bufB (256), out=g_bufA
template<int LAYER, int K>
__global__ void __launch_bounds__(256)
k_gemm(const float* __restrict__ xin,
       const float* __restrict__ B1, const float* __restrict__ B2,
       const float* __restrict__ bias, int M) {
    const float* __restrict__ A1 = g_agg;
    const float* __restrict__ A2 =
        (LAYER == 1) ? xin : (LAYER == 2 ? (const float*)g_bufA : (const float*)g_bufB);
    float* __restrict__ C = (LAYER == 2) ? g_bufB : g_bufA;

    __shared__ float As[16][68];
    __shared__ float Bs[16][68];

    const int tid = threadIdx.x;
    const int tx = tid & 15;          // 0..15 -> N
    const int ty = tid >> 4;          // 0..15 -> M
    const int m0 = blockIdx.x * 64;
    const int n0 = blockIdx.y * 64;

    // A loader: thread -> row m (tid>>2), float4 chunk kq (tid&3)
    const int am = tid >> 2;
    const int akq = tid & 3;
    // B loader: thread -> k row (tid>>4), float4 chunk nq (tid&15)
    const int bkr = tid >> 4;
    const int bnq = tid & 15;

    float c[4][4];
#pragma unroll
    for (int i = 0; i < 4; ++i)
#pragma unroll
        for (int j = 0; j < 4; ++j) c[i][j] = 0.f;

    for (int kk = 0; kk < 2 * K; kk += 16) {
        const bool p0 = (kk < K);
        const int ko = p0 ? kk : kk - K;
        const float* __restrict__ Asrc = p0 ? A1 : A2;
        const float* __restrict__ Bsrc = p0 ? B1 : B2;

        // load A tile 64x16 (transposed into As[k][m])
        {
            int r = m0 + am;
            float4 v = make_float4(0.f, 0.f, 0.f, 0.f);
            if (r < M)
                v = *(const float4*)(Asrc + (size_t)r * K + ko + akq * 4);
            As[akq * 4 + 0][am] = v.x;
            As[akq * 4 + 1][am] = v.y;
            As[akq * 4 + 2][am] = v.z;
            As[akq * 4 + 3][am] = v.w;
        }
        // load B tile 16x64
        {
            float4 w = *(const float4*)(Bsrc + (size_t)(ko + bkr) * DH + n0 + bnq * 4);
            *(float4*)&Bs[bkr][bnq * 4] = w;
        }
        __syncthreads();

#pragma unroll
        for (int k = 0; k < 16; ++k) {
            float4 a = *(const float4*)&As[k][ty * 4];
            float4 b = *(const float4*)&Bs[k][tx * 4];
            float av[4] = {a.x, a.y, a.z, a.w};
            float bv[4] = {b.x, b.y, b.z, b.w};
#pragma unroll
            for (int i = 0; i < 4; ++i)
#pragma unroll
                for (int j = 0; j < 4; ++j)
                    c[i][j] = fmaf(av[i], bv[j], c[i][j]);
        }
        __syncthreads();
    }

    float4 bb = *(const float4*)(bias + n0 + tx * 4);
    float bv[4] = {bb.x, bb.y, bb.z, bb.w};
#pragma unroll
    for (int i = 0; i < 4; ++i) {
        int r = m0 + ty * 4 + i;
        if (r < M) {
            float4 o;
            o.x = fmaxf(c[i][0] + bv[0], 0.f);
            o.y = fmaxf(c[i][1] + bv[1], 0.f);
            o.z = fmaxf(c[i][2] + bv[2], 0.f);
            o.w = fmaxf(c[i][3] + bv[3], 0.f);
            *(float4*)(C + (size_t)r * DH + n0 + tx * 4) = o;
        }
    }
}

// ---------------- pooling ----------------
__global__ void k_pool(const int* __restrict__ batch,
                       float* __restrict__ out, int n) {
    int i = blockIdx.x;
    if (i >= n) return;
    int t = threadIdx.x;
    int b = batch[i];
    atomicAdd(&out[(size_t)b * DH + t], g_bufA[(size_t)i * DH + t]);
    if (t == 0) atomicAdd(&g_gcnt[b], 1.f);
}

__global__ void k_pool_div(float* __restrict__ out) {
    int i = blockIdx.x * blockDim.x + threadIdx.x;
    if (i < NG * DH) {
        float cnt = g_gcnt[i / DH];
        out[i] = out[i] / fmaxf(cnt, 1.f);
    }
}

// ---------------- launch ----------------
extern "C" void kernel_launch(void* const* d_in, const int* in_sizes, int n_in,
                              void* d_out, int out_size) {
    const float* x       = (const float*)d_in[0];
    const int*   ei      = (const int*)d_in[1];
    const int*   batch   = (const int*)d_in[2];
    const float* W1_rel  = (const float*)d_in[3];
    const float* W1_root = (const float*)d_in[4];
    const float* b1      = (const float*)d_in[5];
    const float* W2_rel  = (const float*)d_in[6];
    const float* W2_root = (const float*)d_in[7];
    const float* b2      = (const float*)d_in[8];
    float* out = (float*)d_out;

    const int N = in_sizes[0] / DIN;
    const int E = in_sizes[1] / 2;
    const int* src = ei;
    const int* dst = ei + E;

    // zero accumulators / counters
    {
        int n = N > NG * DH ? N : NG * DH;
        k_zero<<<(n + 255) / 256, 256>>>(out, N);
    }
    // CSR build
    k_hist<<<(E + 255) / 256, 256>>>(dst, E);
    k_scan<<<1, 1024>>>(N);
    k_fill<<<(E + 255) / 256, 256>>>(src, dst, E);

    // handcrafted column sums
    k_colsum<<<512, DIN>>>(x, N);
    k_hand<<<1, DIN>>>(out);

    dim3 ggrid((N + 63) / 64, DH / 64);

    // layer 1
    k_agg<DIN, 0><<<(N + 7) / 8, 256>>>(x, N);
    k_gemm<1, DIN><<<ggrid, 256>>>(x, W1_rel, W1_root, b1, N);
    // layer 2
    k_agg<DH, 1><<<(N + 7) / 8, 256>>>(nullptr, N);
    k_gemm<2, DH><<<ggrid, 256>>>(nullptr, W2_rel, W2_root, b2, N);
    // layer 3
    k_agg<DH, 2><<<(N + 7) / 8, 256>>>(nullptr, N);
    k_gemm<3, DH><<<ggrid, 256>>>(nullptr, W2_rel, W2_root, b2, N);

    // global mean pool
    k_pool<<<N, DH>>>(batch, out, N);
    k_pool_div<<<(NG * DH + 255) / 256, 256>>>(out);
}

// round 4
// speedup vs baseline: 1.5422x; 1.5422x over previous
#include <cuda_runtime.h>
#include <cuda_bf16.h>
#include <math.h>

#define NMAX 50000
#define EMAX 800000
#define DH   256
#define DIN  128
#define NG   64

// ---------------- device scratch (no allocations allowed) ----------------
__device__ float g_h[(size_t)NMAX * DH];          // f32 activations (current layer)
__device__ __nv_bfloat16 g_aggH[(size_t)NMAX * DH];
__device__ __nv_bfloat16 g_aggL[(size_t)NMAX * DH];
__device__ __nv_bfloat16 g_r0H[(size_t)NMAX * DH];
__device__ __nv_bfloat16 g_r0L[(size_t)NMAX * DH];
__device__ __nv_bfloat16 g_r1H[(size_t)NMAX * DH];
__device__ __nv_bfloat16 g_r1L[(size_t)NMAX * DH];
// transposed split weights: Bt[n][k2], k2 = [rel | root]
__device__ __nv_bfloat16 g_Bt1H[DH * 2 * DIN];
__device__ __nv_bfloat16 g_Bt1L[DH * 2 * DIN];
__device__ __nv_bfloat16 g_Bt2H[DH * 2 * DH];
__device__ __nv_bfloat16 g_Bt2L[DH * 2 * DH];

__device__ int   g_rowptr[NMAX + 1];
__device__ int   g_cnt [NMAX];
__device__ int   g_cnt2[NMAX];
__device__ int   g_col [EMAX];
__device__ float g_colsum[DIN];
__device__ float g_gcnt[NG];

// ---------------- helpers ----------------
__device__ __forceinline__ unsigned pack2(float a, float b) {
    __nv_bfloat16 ha = __float2bfloat16(a);
    __nv_bfloat16 hb = __float2bfloat16(b);
    return (unsigned)__bfloat16_as_ushort(ha) |
           ((unsigned)__bfloat16_as_ushort(hb) << 16);
}
__device__ __forceinline__ void split4(float4 v, uint2& h, uint2& l) {
    __nv_bfloat16 h0 = __float2bfloat16(v.x); float r0 = v.x - __bfloat162float(h0);
    __nv_bfloat16 h1 = __float2bfloat16(v.y); float r1 = v.y - __bfloat162float(h1);
    __nv_bfloat16 h2 = __float2bfloat16(v.z); float r2 = v.z - __bfloat162float(h2);
    __nv_bfloat16 h3 = __float2bfloat16(v.w); float r3 = v.w - __bfloat162float(h3);
    h.x = (unsigned)__bfloat16_as_ushort(h0) | ((unsigned)__bfloat16_as_ushort(h1) << 16);
    h.y = (unsigned)__bfloat16_as_ushort(h2) | ((unsigned)__bfloat16_as_ushort(h3) << 16);
    l.x = pack2(r0, r1);
    l.y = pack2(r2, r3);
}

#define MMA(c, a, b) \
    asm volatile("mma.sync.aligned.m16n8k16.row.col.f32.bf16.bf16.f32 " \
                 "{%0,%1,%2,%3},{%4,%5,%6,%7},{%8,%9},{%0,%1,%2,%3};" \
                 : "+f"((c)[0]), "+f"((c)[1]), "+f"((c)[2]), "+f"((c)[3]) \
                 : "r"((a)[0]), "r"((a)[1]), "r"((a)[2]), "r"((a)[3]), \
                   "r"((b)[0]), "r"((b)[1]))

// ---------------- zero scratch + output accumulators ----------------
__global__ void k_zero(float* __restrict__ out, int n) {
    int i = blockIdx.x * blockDim.x + threadIdx.x;
    if (i < n)       { g_cnt[i] = 0; g_cnt2[i] = 0; }
    if (i < NG * DH) out[i] = 0.f;
    if (i < DIN)     g_colsum[i] = 0.f;
    if (i < NG)      g_gcnt[i] = 0.f;
}

// ---------------- CSR build ----------------
__global__ void k_hist(const int* __restrict__ dst, int E) {
    int e = blockIdx.x * blockDim.x + threadIdx.x;
    if (e < E) atomicAdd(&g_cnt[dst[e]], 1);
}

__global__ void k_scan(int n) {
    __shared__ int sh[1024];
    int t = threadIdx.x;
    int C = (n + 1023) >> 10;
    int b = t * C;
    int e = min(n, b + C);
    int s = 0;
    for (int i = b; i < e; ++i) s += g_cnt[i];
    sh[t] = s;
    __syncthreads();
    for (int off = 1; off < 1024; off <<= 1) {
        int v = (t >= off) ? sh[t - off] : 0;
        __syncthreads();
        sh[t] += v;
        __syncthreads();
    }
    int run = (t == 0) ? 0 : sh[t - 1];
    for (int i = b; i < e; ++i) { g_rowptr[i] = run; run += g_cnt[i]; }
    if (t == 1023) g_rowptr[n] = sh[1023];
}

__global__ void k_fill(const int* __restrict__ src,
                       const int* __restrict__ dst, int E) {
    int e = blockIdx.x * blockDim.x + threadIdx.x;
    if (e < E) {
        int d = dst[e];
        int pos = g_rowptr[d] + atomicAdd(&g_cnt2[d], 1);
        g_col[pos] = src[e];
    }
}

// ---------------- weight prep: transpose + bf16 hi/lo split ----------------
__global__ void k_prep(const float* __restrict__ W1_rel, const float* __restrict__ W1_root,
                       const float* __restrict__ W2_rel, const float* __restrict__ W2_root) {
    int i = blockIdx.x * 256 + threadIdx.x;
    const int n1 = DH * 2 * DIN;  // 65536
    const int n2 = DH * 2 * DH;   // 131072
    if (i < n1) {
        int n = i / (2 * DIN), k2 = i % (2 * DIN);
        float w = (k2 < DIN) ? W1_rel[(size_t)k2 * DH + n]
                             : W1_root[(size_t)(k2 - DIN) * DH + n];
        __nv_bfloat16 h = __float2bfloat16(w);
        g_Bt1H[i] = h;
        g_Bt1L[i] = __float2bfloat16(w - __bfloat162float(h));
    } else if (i < n1 + n2) {
        int j = i - n1;
        int n = j / (2 * DH), k2 = j % (2 * DH);
        float w = (k2 < DH) ? W2_rel[(size_t)k2 * DH + n]
                            : W2_root[(size_t)(k2 - DH) * DH + n];
        __nv_bfloat16 h = __float2bfloat16(w);
        g_Bt2H[j] = h;
        g_Bt2L[j] = __float2bfloat16(w - __bfloat162float(h));
    }
}

// ---------------- convert x -> r0 bf16 hi/lo (row stride DIN) ----------------
__global__ void k_convert_x(const float* __restrict__ x, int total) {
    int i = blockIdx.x * blockDim.x + threadIdx.x;
    if (i < total) {
        float v = x[i];
        __nv_bfloat16 h = __float2bfloat16(v);
        g_r0H[i] = h;
        g_r0L[i] = __float2bfloat16(v - __bfloat162float(h));
    }
}

// ---------------- handcrafted: column sums of x ----------------
__global__ void k_colsum(const float* __restrict__ x, int n) {
    int t = threadIdx.x;
    float acc = 0.f;
    for (int r = blockIdx.x; r < n; r += gridDim.x)
        acc += x[(size_t)r * DIN + t];
    atomicAdd(&g_colsum[t], acc);
}

__global__ void k_hand(float* __restrict__ out) {
    __shared__ float sh[DIN];
    int t = threadIdx.x;
    float v = g_colsum[t];
    sh[t] = v;
    __syncthreads();
    for (int o = 64; o > 0; o >>= 1) {
        if (t < o) sh[t] += sh[t + o];
        __syncthreads();
    }
    float total = sh[0];
    out[NG * DH + t] = v / total;
    if (t == 0) out[NG * DH + DIN] = logf(total);
}

// ---------------- aggregation: warp per node, writes bf16 hi/lo ----------------
// SRC: 0 = external x (D=128), 1 = g_h (D=256)
template<int D, int SRC>
__global__ void k_agg_bf(const float* __restrict__ xin, int n) {
    const float* __restrict__ h = (SRC == 0) ? xin : (const float*)g_h;
    int node = blockIdx.x * 8 + (threadIdx.x >> 5);
    int lane = threadIdx.x & 31;
    if (node >= n) return;
    int s = g_rowptr[node];
    int e = g_rowptr[node + 1];
    float4 a0 = make_float4(0.f, 0.f, 0.f, 0.f);
    float4 a1 = make_float4(0.f, 0.f, 0.f, 0.f);
    int i = s;
    for (; i + 2 <= e; i += 2) {
        int u = g_col[i], v = g_col[i + 1];
        const float4* pu = (const float4*)(h + (size_t)u * D);
        const float4* pv = (const float4*)(h + (size_t)v * D);
        float4 x0 = pu[lane];
        float4 y0 = pv[lane];
        a0.x += x0.x + y0.x; a0.y += x0.y + y0.y;
        a0.z += x0.z + y0.z; a0.w += x0.w + y0.w;
        if (D == 256) {
            float4 x1 = pu[lane + 32];
            float4 y1 = pv[lane + 32];
            a1.x += x1.x + y1.x; a1.y += x1.y + y1.y;
            a1.z += x1.z + y1.z; a1.w += x1.w + y1.w;
        }
    }
    if (i < e) {
        int u = g_col[i];
        const float4* pu = (const float4*)(h + (size_t)u * D);
        float4 x0 = pu[lane];
        a0.x += x0.x; a0.y += x0.y; a0.z += x0.z; a0.w += x0.w;
        if (D == 256) {
            float4 x1 = pu[lane + 32];
            a1.x += x1.x; a1.y += x1.y; a1.z += x1.z; a1.w += x1.w;
        }
    }
    uint2 hh, ll;
    split4(a0, hh, ll);
    ((uint2*)(g_aggH + (size_t)node * D))[lane] = hh;
    ((uint2*)(g_aggL + (size_t)node * D))[lane] = ll;
    if (D == 256) {
        split4(a1, hh, ll);
        ((uint2*)(g_aggH + (size_t)node * D))[lane + 32] = hh;
        ((uint2*)(g_aggL + (size_t)node * D))[lane + 32] = ll;
    }
}

// ---------------- tensor-core GEMM ----------------
// C = relu([aggbf | rootbf] @ Bt^T + bias), split-bf16 3-product mma.sync.
// BM=128, BN=64, BK=32, 256 threads, warp tile 32x32 (warps 4Mx2N).
//   LAYER 1: K=128, root=g_r0 (stride 128), Bt=g_Bt1, out bf16 -> g_r1
//   LAYER 2: K=256, root=g_r1,              Bt=g_Bt2, out bf16 -> g_r0
//   LAYER 3: K=256, root=g_r0,              Bt=g_Bt2, no bf16 out
template<int LAYER>
__global__ void __launch_bounds__(256)
k_gemm(const float* __restrict__ bias, int M) {
    constexpr int K  = (LAYER == 1) ? DIN : DH;
    constexpr int K2 = 2 * K;
    constexpr bool WBF = (LAYER != 3);

    const __nv_bfloat16* __restrict__ rootH = (LAYER == 2) ? g_r1H : g_r0H;
    const __nv_bfloat16* __restrict__ rootL = (LAYER == 2) ? g_r1L : g_r0L;
    const __nv_bfloat16* __restrict__ BtH   = (LAYER == 1) ? g_Bt1H : g_Bt2H;
    const __nv_bfloat16* __restrict__ BtL   = (LAYER == 1) ? g_Bt1L : g_Bt2L;
    __nv_bfloat16* __restrict__ outH = (LAYER == 1) ? g_r1H : g_r0H;
    __nv_bfloat16* __restrict__ outL = (LAYER == 1) ? g_r1L : g_r0L;
    float* __restrict__ Cout = g_h;

    __shared__ __nv_bfloat16 AsH[128][40];
    __shared__ __nv_bfloat16 AsL[128][40];
    __shared__ __nv_bfloat16 BsH[64][40];
    __shared__ __nv_bfloat16 BsL[64][40];

    const int tid  = threadIdx.x;
    const int lane = tid & 31;
    const int warp = tid >> 5;
    const int wm   = warp >> 1;   // 0..3 -> M offset wm*32
    const int wn   = warp & 1;    // 0..1 -> N offset wn*32
    const int gID  = lane >> 2;
    const int tg   = lane & 3;
    const int m0   = blockIdx.x * 128;
    const int n0   = blockIdx.y * 64;

    const int arow = tid >> 2;    // 0..63 (+64 on second pass)
    const int aq   = tid & 3;     // 16B chunk within 32-col row

    float c[2][4][4];
#pragma unroll
    for (int mt = 0; mt < 2; ++mt)
#pragma unroll
        for (int nt = 0; nt < 4; ++nt)
#pragma unroll
            for (int q = 0; q < 4; ++q) c[mt][nt][q] = 0.f;

    for (int kk = 0; kk < K2; kk += 32) {
        const bool first = (kk < K);
        const __nv_bfloat16* __restrict__ srcH = first ? g_aggH : rootH;
        const __nv_bfloat16* __restrict__ srcL = first ? g_aggL : rootL;
        const int col = first ? kk : kk - K;

        // A tile: 128x32, hi+lo
#pragma unroll
        for (int i = 0; i < 2; ++i) {
            int r = arow + i * 64;
            int gr = m0 + r;
            uint4 vh = make_uint4(0, 0, 0, 0), vl = make_uint4(0, 0, 0, 0);
            if (gr < M) {
                vh = *(const uint4*)(srcH + (size_t)gr * K + col + aq * 8);
                vl = *(const uint4*)(srcL + (size_t)gr * K + col + aq * 8);
            }
            *(uint4*)&AsH[r][aq * 8] = vh;
            *(uint4*)&AsL[r][aq * 8] = vl;
        }
        // B tile (already transposed in global): 64x32, hi+lo
        {
            int br = tid >> 2;
            *(uint4*)&BsH[br][aq * 8] =
                *(const uint4*)(BtH + (size_t)(n0 + br) * K2 + kk + aq * 8);
            *(uint4*)&BsL[br][aq * 8] =
                *(const uint4*)(BtL + (size_t)(n0 + br) * K2 + kk + aq * 8);
        }
        __syncthreads();

#pragma unroll
        for (int ks = 0; ks < 32; ks += 16) {
            unsigned aH[2][4], aL[2][4], bH[4][2], bL[4][2];
#pragma unroll
            for (int mt = 0; mt < 2; ++mt) {
                int rr = wm * 32 + mt * 16 + gID;
                aH[mt][0] = *(const unsigned*)&AsH[rr][ks + tg * 2];
                aH[mt][1] = *(const unsigned*)&AsH[rr + 8][ks + tg * 2];
                aH[mt][2] = *(const unsigned*)&AsH[rr][ks + tg * 2 + 8];
                aH[mt][3] = *(const unsigned*)&AsH[rr + 8][ks + tg * 2 + 8];
                aL[mt][0] = *(const unsigned*)&AsL[rr][ks + tg * 2];
                aL[mt][1] = *(const unsigned*)&AsL[rr + 8][ks + tg * 2];
                aL[mt][2] = *(const unsigned*)&AsL[rr][ks + tg * 2 + 8];
                aL[mt][3] = *(const unsigned*)&AsL[rr + 8][ks + tg * 2 + 8];
            }
#pragma unroll
            for (int nt = 0; nt < 4; ++nt) {
                int nn = wn * 32 + nt * 8 + gID;
                bH[nt][0] = *(const unsigned*)&BsH[nn][ks + tg * 2];
                bH[nt][1] = *(const unsigned*)&BsH[nn][ks + tg * 2 + 8];
                bL[nt][0] = *(const unsigned*)&BsL[nn][ks + tg * 2];
                bL[nt][1] = *(const unsigned*)&BsL[nn][ks + tg * 2 + 8];
            }
#pragma unroll
            for (int mt = 0; mt < 2; ++mt)
#pragma unroll
                for (int nt = 0; nt < 4; ++nt) {
                    MMA(c[mt][nt], aH[mt], bH[nt]);
                    MMA(c[mt][nt], aL[mt], bH[nt]);
                    MMA(c[mt][nt], aH[mt], bL[nt]);
                }
        }
        __syncthreads();
    }

    // epilogue: bias + relu, write f32 h and (optionally) bf16 hi/lo
#pragma unroll
    for (int nt = 0; nt < 4; ++nt) {
        int cn = n0 + wn * 32 + nt * 8 + tg * 2;
        float2 bb = *(const float2*)(bias + cn);
#pragma unroll
        for (int mt = 0; mt < 2; ++mt) {
            int r0 = m0 + wm * 32 + mt * 16 + gID;
            int r1 = r0 + 8;
            float v00 = fmaxf(c[mt][nt][0] + bb.x, 0.f);
            float v01 = fmaxf(c[mt][nt][1] + bb.y, 0.f);
            float v10 = fmaxf(c[mt][nt][2] + bb.x, 0.f);
            float v11 = fmaxf(c[mt][nt][3] + bb.y, 0.f);
            if (r0 < M) {
                *(float2*)(Cout + (size_t)r0 * DH + cn) = make_float2(v00, v01);
                if (WBF) {
                    __nv_bfloat16 h0 = __float2bfloat16(v00);
                    __nv_bfloat16 h1 = __float2bfloat16(v01);
                    *(unsigned*)(outH + (size_t)r0 * DH + cn) =
                        (unsigned)__bfloat16_as_ushort(h0) |
                        ((unsigned)__bfloat16_as_ushort(h1) << 16);
                    *(unsigned*)(outL + (size_t)r0 * DH + cn) =
                        pack2(v00 - __bfloat162float(h0), v01 - __bfloat162float(h1));
                }
            }
            if (r1 < M) {
                *(float2*)(Cout + (size_t)r1 * DH + cn) = make_float2(v10, v11);
                if (WBF) {
                    __nv_bfloat16 h0 = __float2bfloat16(v10);
                    __nv_bfloat16 h1 = __float2bfloat16(v11);
                    *(unsigned*)(outH + (size_t)r1 * DH + cn) =
                        (unsigned)__bfloat16_as_ushort(h0) |
                        ((unsigned)__bfloat16_as_ushort(h1) << 16);
                    *(unsigned*)(outL + (size_t)r1 * DH + cn) =
                        pack2(v10 - __bfloat162float(h0), v11 - __bfloat162float(h1));
                }
            }
        }
    }
}

// ---------------- pooling ----------------
__global__ void k_pool(const int* __restrict__ batch,
                       float* __restrict__ out, int n) {
    int i = blockIdx.x;
    if (i >= n) return;
    int t = threadIdx.x;
    int b = batch[i];
    atomicAdd(&out[(size_t)b * DH + t], g_h[(size_t)i * DH + t]);
    if (t == 0) atomicAdd(&g_gcnt[b], 1.f);
}

__global__ void k_pool_div(float* __restrict__ out) {
    int i = blockIdx.x * blockDim.x + threadIdx.x;
    if (i < NG * DH) {
        float cnt = g_gcnt[i / DH];
        out[i] = out[i] / fmaxf(cnt, 1.f);
    }
}

// ---------------- launch ----------------
extern "C" void kernel_launch(void* const* d_in, const int* in_sizes, int n_in,
                              void* d_out, int out_size) {
    const float* x       = (const float*)d_in[0];
    const int*   ei      = (const int*)d_in[1];
    const int*   batch   = (const int*)d_in[2];
    const float* W1_rel  = (const float*)d_in[3];
    const float* W1_root = (const float*)d_in[4];
    const float* b1      = (const float*)d_in[5];
    const float* W2_rel  = (const float*)d_in[6];
    const float* W2_root = (const float*)d_in[7];
    const float* b2      = (const float*)d_in[8];
    float* out = (float*)d_out;

    const int N = in_sizes[0] / DIN;
    const int E = in_sizes[1] / 2;
    const int* src = ei;
    const int* dst = ei + E;

    {
        int n = N > NG * DH ? N : NG * DH;
        k_zero<<<(n + 255) / 256, 256>>>(out, N);
    }
    // CSR build
    k_hist<<<(E + 255) / 256, 256>>>(dst, E);
    k_scan<<<1, 1024>>>(N);
    k_fill<<<(E + 255) / 256, 256>>>(src, dst, E);

    // weight prep + x conversion
    k_prep<<<(DH * 2 * DIN + DH * 2 * DH + 255) / 256, 256>>>(W1_rel, W1_root, W2_rel, W2_root);
    k_convert_x<<<(N * DIN + 255) / 256, 256>>>(x, N * DIN);

    // handcrafted
    k_colsum<<<512, DIN>>>(x, N);
    k_hand<<<1, DIN>>>(out);

    dim3 ggrid((N + 127) / 128, DH / 64);

    // layer 1
    k_agg_bf<DIN, 0><<<(N + 7) / 8, 256>>>(x, N);
    k_gemm<1><<<ggrid, 256>>>(b1, N);
    // layer 2
    k_agg_bf<DH, 1><<<(N + 7) / 8, 256>>>(nullptr, N);
    k_gemm<2><<<ggrid, 256>>>(b2, N);
    // layer 3
    k_agg_bf<DH, 1><<<(N + 7) / 8, 256>>>(nullptr, N);
    k_gemm<3><<<ggrid, 256>>>(b2, N);

    // global mean pool
    k_pool<<<N, DH>>>(batch, out, N);
    k_pool_div<<<(NG * DH + 255) / 256, 256>>>(out);
}

// round 5
// speedup vs baseline: 1.7553x; 1.1382x over previous
#include <cuda_runtime.h>
#include <cuda_bf16.h>
#include <math.h>

#define NMAX 50000
#define EMAX 800000
#define DH   256
#define DIN  128
#define NG   64

// ---------------- device scratch ----------------
__device__ float g_h[(size_t)NMAX * DH];          // f32 activations (current layer)
__device__ __nv_bfloat16 g_aggH[(size_t)NMAX * DH];
__device__ __nv_bfloat16 g_aggL[(size_t)NMAX * DH];
__device__ __nv_bfloat16 g_r0H[(size_t)NMAX * DH];
__device__ __nv_bfloat16 g_r0L[(size_t)NMAX * DH];
__device__ __nv_bfloat16 g_r1H[(size_t)NMAX * DH];
__device__ __nv_bfloat16 g_r1L[(size_t)NMAX * DH];
// transposed split weights: Bt[n][k2], k2 = [rel | root]
__device__ __nv_bfloat16 g_Bt1H[DH * 2 * DIN];
__device__ __nv_bfloat16 g_Bt1L[DH * 2 * DIN];
__device__ __nv_bfloat16 g_Bt2H[DH * 2 * DH];
__device__ __nv_bfloat16 g_Bt2L[DH * 2 * DH];

__device__ int   g_rowptr[NMAX + 1];
__device__ int   g_cnt [NMAX];
__device__ int   g_cnt2[NMAX];
__device__ int   g_col [EMAX];
__device__ float g_colsum[DIN];
__device__ float g_gcnt[NG];

// ---------------- helpers ----------------
__device__ __forceinline__ unsigned pack2(float a, float b) {
    __nv_bfloat16 ha = __float2bfloat16(a);
    __nv_bfloat16 hb = __float2bfloat16(b);
    return (unsigned)__bfloat16_as_ushort(ha) |
           ((unsigned)__bfloat16_as_ushort(hb) << 16);
}
__device__ __forceinline__ void split4(float4 v, uint2& h, uint2& l) {
    __nv_bfloat16 h0 = __float2bfloat16(v.x); float r0 = v.x - __bfloat162float(h0);
    __nv_bfloat16 h1 = __float2bfloat16(v.y); float r1 = v.y - __bfloat162float(h1);
    __nv_bfloat16 h2 = __float2bfloat16(v.z); float r2 = v.z - __bfloat162float(h2);
    __nv_bfloat16 h3 = __float2bfloat16(v.w); float r3 = v.w - __bfloat162float(h3);
    h.x = (unsigned)__bfloat16_as_ushort(h0) | ((unsigned)__bfloat16_as_ushort(h1) << 16);
    h.y = (unsigned)__bfloat16_as_ushort(h2) | ((unsigned)__bfloat16_as_ushort(h3) << 16);
    l.x = pack2(r0, r1);
    l.y = pack2(r2, r3);
}

#define MMA(c, a, b) \
    asm volatile("mma.sync.aligned.m16n8k16.row.col.f32.bf16.bf16.f32 " \
                 "{%0,%1,%2,%3},{%4,%5,%6,%7},{%8,%9},{%0,%1,%2,%3};" \
                 : "+f"((c)[0]), "+f"((c)[1]), "+f"((c)[2]), "+f"((c)[3]) \
                 : "r"((a)[0]), "r"((a)[1]), "r"((a)[2]), "r"((a)[3]), \
                   "r"((b)[0]), "r"((b)[1]))

__device__ __forceinline__ void ldsm4(unsigned* r, const __nv_bfloat16* p) {
    unsigned a = (unsigned)__cvta_generic_to_shared((void*)p);
    asm volatile("ldmatrix.sync.aligned.m8n8.x4.shared.b16 {%0,%1,%2,%3}, [%4];"
                 : "=r"(r[0]), "=r"(r[1]), "=r"(r[2]), "=r"(r[3]) : "r"(a));
}
__device__ __forceinline__ void cpa16(__nv_bfloat16* dst, const __nv_bfloat16* src, bool pred) {
    unsigned d = (unsigned)__cvta_generic_to_shared((void*)dst);
    int sz = pred ? 16 : 0;
    asm volatile("cp.async.cg.shared.global [%0], [%1], 16, %2;"
                 :: "r"(d), "l"(src), "r"(sz));
}
#define CP_COMMIT() asm volatile("cp.async.commit_group;")
#define CP_WAIT1()  asm volatile("cp.async.wait_group 1;")

// ---------------- zero scratch + output accumulators ----------------
__global__ void k_zero(float* __restrict__ out, int n) {
    int i = blockIdx.x * blockDim.x + threadIdx.x;
    if (i < n)       { g_cnt[i] = 0; g_cnt2[i] = 0; }
    if (i < NG * DH) out[i] = 0.f;
    if (i < DIN)     g_colsum[i] = 0.f;
    if (i < NG)      g_gcnt[i] = 0.f;
}

// ---------------- CSR build ----------------
__global__ void k_hist(const int* __restrict__ dst, int E) {
    int e = blockIdx.x * blockDim.x + threadIdx.x;
    if (e < E) atomicAdd(&g_cnt[dst[e]], 1);
}

__global__ void k_scan(int n) {
    __shared__ int sh[1024];
    int t = threadIdx.x;
    int C = (n + 1023) >> 10;
    int b = t * C;
    int e = min(n, b + C);
    int s = 0;
    for (int i = b; i < e; ++i) s += g_cnt[i];
    sh[t] = s;
    __syncthreads();
    for (int off = 1; off < 1024; off <<= 1) {
        int v = (t >= off) ? sh[t - off] : 0;
        __syncthreads();
        sh[t] += v;
        __syncthreads();
    }
    int run = (t == 0) ? 0 : sh[t - 1];
    for (int i = b; i < e; ++i) { g_rowptr[i] = run; run += g_cnt[i]; }
    if (t == 1023) g_rowptr[n] = sh[1023];
}

__global__ void k_fill(const int* __restrict__ src,
                       const int* __restrict__ dst, int E) {
    int e = blockIdx.x * blockDim.x + threadIdx.x;
    if (e < E) {
        int d = dst[e];
        int pos = g_rowptr[d] + atomicAdd(&g_cnt2[d], 1);
        g_col[pos] = src[e];
    }
}

// ---------------- weight prep: transpose + bf16 hi/lo split ----------------
__global__ void k_prep(const float* __restrict__ W1_rel, const float* __restrict__ W1_root,
                       const float* __restrict__ W2_rel, const float* __restrict__ W2_root) {
    int i = blockIdx.x * 256 + threadIdx.x;
    const int n1 = DH * 2 * DIN;
    const int n2 = DH * 2 * DH;
    if (i < n1) {
        int n = i / (2 * DIN), k2 = i % (2 * DIN);
        float w = (k2 < DIN) ? W1_rel[(size_t)k2 * DH + n]
                             : W1_root[(size_t)(k2 - DIN) * DH + n];
        __nv_bfloat16 h = __float2bfloat16(w);
        g_Bt1H[i] = h;
        g_Bt1L[i] = __float2bfloat16(w - __bfloat162float(h));
    } else if (i < n1 + n2) {
        int j = i - n1;
        int n = j / (2 * DH), k2 = j % (2 * DH);
        float w = (k2 < DH) ? W2_rel[(size_t)k2 * DH + n]
                            : W2_root[(size_t)(k2 - DH) * DH + n];
        __nv_bfloat16 h = __float2bfloat16(w);
        g_Bt2H[j] = h;
        g_Bt2L[j] = __float2bfloat16(w - __bfloat162float(h));
    }
}

// ---------------- x prep: bf16 hi/lo convert + column sums (fused) ----------------
__global__ void k_xprep(const float* __restrict__ x, int n) {
    int t = threadIdx.x;  // 128 threads = DIN channels
    float acc = 0.f;
    for (int r = blockIdx.x; r < n; r += gridDim.x) {
        float v = x[(size_t)r * DIN + t];
        acc += v;
        __nv_bfloat16 h = __float2bfloat16(v);
        g_r0H[(size_t)r * DIN + t] = h;
        g_r0L[(size_t)r * DIN + t] = __float2bfloat16(v - __bfloat162float(h));
    }
    atomicAdd(&g_colsum[t], acc);
}

__global__ void k_hand(float* __restrict__ out) {
    __shared__ float sh[DIN];
    int t = threadIdx.x;
    float v = g_colsum[t];
    sh[t] = v;
    __syncthreads();
    for (int o = 64; o > 0; o >>= 1) {
        if (t < o) sh[t] += sh[t + o];
        __syncthreads();
    }
    float total = sh[0];
    out[NG * DH + t] = v / total;
    if (t == 0) out[NG * DH + DIN] = logf(total);
}

// ---------------- aggregation: warp per node, writes bf16 hi/lo ----------------
template<int D, int SRC>
__global__ void k_agg_bf(const float* __restrict__ xin, int n) {
    const float* __restrict__ h = (SRC == 0) ? xin : (const float*)g_h;
    int node = blockIdx.x * 8 + (threadIdx.x >> 5);
    int lane = threadIdx.x & 31;
    if (node >= n) return;
    int s = g_rowptr[node];
    int e = g_rowptr[node + 1];
    float4 a0 = make_float4(0.f, 0.f, 0.f, 0.f);
    float4 a1 = make_float4(0.f, 0.f, 0.f, 0.f);
    int i = s;
    for (; i + 2 <= e; i += 2) {
        int u = g_col[i], v = g_col[i + 1];
        const float4* pu = (const float4*)(h + (size_t)u * D);
        const float4* pv = (const float4*)(h + (size_t)v * D);
        float4 x0 = pu[lane];
        float4 y0 = pv[lane];
        a0.x += x0.x + y0.x; a0.y += x0.y + y0.y;
        a0.z += x0.z + y0.z; a0.w += x0.w + y0.w;
        if (D == 256) {
            float4 x1 = pu[lane + 32];
            float4 y1 = pv[lane + 32];
            a1.x += x1.x + y1.x; a1.y += x1.y + y1.y;
            a1.z += x1.z + y1.z; a1.w += x1.w + y1.w;
        }
    }
    if (i < e) {
        int u = g_col[i];
        const float4* pu = (const float4*)(h + (size_t)u * D);
        float4 x0 = pu[lane];
        a0.x += x0.x; a0.y += x0.y; a0.z += x0.z; a0.w += x0.w;
        if (D == 256) {
            float4 x1 = pu[lane + 32];
            a1.x += x1.x; a1.y += x1.y; a1.z += x1.z; a1.w += x1.w;
        }
    }
    uint2 hh, ll;
    split4(a0, hh, ll);
    ((uint2*)(g_aggH + (size_t)node * D))[lane] = hh;
    ((uint2*)(g_aggL + (size_t)node * D))[lane] = ll;
    if (D == 256) {
        split4(a1, hh, ll);
        ((uint2*)(g_aggH + (size_t)node * D))[lane + 32] = hh;
        ((uint2*)(g_aggL + (size_t)node * D))[lane + 32] = ll;
    }
}

// ---------------- pipelined tensor-core GEMM ----------------
// C = relu([aggbf | rootbf] @ Bt^T + bias), split-bf16 3-product mma.sync.
// BM=128, BN=64, BK=32, 256 threads, warps 4Mx2N (32x32 warp tile).
// 3-stage cp.async pipeline, ldmatrix fragment loads.
// dyn smem per stage (bf16 elems): AsH@0 AsL@5120 BsH@10240 BsL@12800; stride 15360.
template<int LAYER>
__global__ void __launch_bounds__(256, 2)
k_gemm(const float* __restrict__ bias, int M) {
    constexpr int K  = (LAYER == 1) ? DIN : DH;
    constexpr int K2 = 2 * K;
    constexpr int T  = K2 / 32;
    constexpr bool WBF = (LAYER != 3);

    const __nv_bfloat16* __restrict__ rootH = (LAYER == 2) ? g_r1H : g_r0H;
    const __nv_bfloat16* __restrict__ rootL = (LAYER == 2) ? g_r1L : g_r0L;
    const __nv_bfloat16* __restrict__ BtH   = (LAYER == 1) ? g_Bt1H : g_Bt2H;
    const __nv_bfloat16* __restrict__ BtL   = (LAYER == 1) ? g_Bt1L : g_Bt2L;
    __nv_bfloat16* __restrict__ outH = (LAYER == 1) ? g_r1H : g_r0H;
    __nv_bfloat16* __restrict__ outL = (LAYER == 1) ? g_r1L : g_r0L;
    float* __restrict__ Cout = g_h;

    extern __shared__ __nv_bfloat16 sm[];

    const int tid  = threadIdx.x;
    const int lane = tid & 31;
    const int warp = tid >> 5;
    const int wm   = warp >> 1;
    const int wn   = warp & 1;
    const int gID  = lane >> 2;
    const int tg   = lane & 3;
    const int m0   = blockIdx.x * 128;
    const int n0   = blockIdx.y * 64;

    const int arow = tid >> 2;    // 0..63
    const int aq   = tid & 3;

    float c[2][4][4];
#pragma unroll
    for (int mt = 0; mt < 2; ++mt)
#pragma unroll
        for (int nt = 0; nt < 4; ++nt)
#pragma unroll
            for (int q = 0; q < 4; ++q) c[mt][nt][q] = 0.f;

    auto load_stage = [&](int it, int s) {
        const bool first = (it * 32 < K);
        const __nv_bfloat16* __restrict__ srcH = first ? g_aggH : rootH;
        const __nv_bfloat16* __restrict__ srcL = first ? g_aggL : rootL;
        const int col = first ? it * 32 : it * 32 - K;
        __nv_bfloat16* st = sm + s * 15360;
#pragma unroll
        for (int i = 0; i < 2; ++i) {
            int r = arow + i * 64;
            int gr = m0 + r;
            bool p = gr < M;
            int grc = p ? gr : 0;
            cpa16(st + r * 40 + aq * 8,        srcH + (size_t)grc * K + col + aq * 8, p);
            cpa16(st + 5120 + r * 40 + aq * 8, srcL + (size_t)grc * K + col + aq * 8, p);
        }
        cpa16(st + 10240 + arow * 40 + aq * 8,
              BtH + (size_t)(n0 + arow) * K2 + it * 32 + aq * 8, true);
        cpa16(st + 12800 + arow * 40 + aq * 8,
              BtL + (size_t)(n0 + arow) * K2 + it * 32 + aq * 8, true);
    };

    const int lrow = lane & 15;
    const int lk   = (lane >> 4) * 8;

    load_stage(0, 0);
    CP_COMMIT();
    load_stage(1, 1);
    CP_COMMIT();

    for (int it = 0; it < T; ++it) {
        int s = it % 3;
        CP_WAIT1();
        __syncthreads();
        if (it + 2 < T) load_stage(it + 2, (it + 2) % 3);
        CP_COMMIT();

        __nv_bfloat16* st = sm + s * 15360;
#pragma unroll
        for (int ks = 0; ks < 32; ks += 16) {
            unsigned aH[2][4], aL[2][4], bH[4][2], bL[4][2];
#pragma unroll
            for (int mt = 0; mt < 2; ++mt) {
                int rr = wm * 32 + mt * 16 + lrow;
                ldsm4(aH[mt], st + rr * 40 + ks + lk);
                ldsm4(aL[mt], st + 5120 + rr * 40 + ks + lk);
            }
#pragma unroll
            for (int nh = 0; nh < 2; ++nh) {
                int nn = wn * 32 + nh * 16 + lrow;
                unsigned r4[4];
                ldsm4(r4, st + 10240 + nn * 40 + ks + lk);
                bH[nh * 2][0] = r4[0]; bH[nh * 2 + 1][0] = r4[1];
                bH[nh * 2][1] = r4[2]; bH[nh * 2 + 1][1] = r4[3];
                ldsm4(r4, st + 12800 + nn * 40 + ks + lk);
                bL[nh * 2][0] = r4[0]; bL[nh * 2 + 1][0] = r4[1];
                bL[nh * 2][1] = r4[2]; bL[nh * 2 + 1][1] = r4[3];
            }
#pragma unroll
            for (int mt = 0; mt < 2; ++mt)
#pragma unroll
                for (int nt = 0; nt < 4; ++nt) {
                    MMA(c[mt][nt], aH[mt], bH[nt]);
                    MMA(c[mt][nt], aL[mt], bH[nt]);
                    MMA(c[mt][nt], aH[mt], bL[nt]);
                }
        }
        __syncthreads();
    }

    // epilogue: bias + relu, write f32 h and (optionally) bf16 hi/lo
#pragma unroll
    for (int nt = 0; nt < 4; ++nt) {
        int cn = n0 + wn * 32 + nt * 8 + tg * 2;
        float2 bb = *(const float2*)(bias + cn);
#pragma unroll
        for (int mt = 0; mt < 2; ++mt) {
            int r0 = m0 + wm * 32 + mt * 16 + gID;
            int r1 = r0 + 8;
            float v00 = fmaxf(c[mt][nt][0] + bb.x, 0.f);
            float v01 = fmaxf(c[mt][nt][1] + bb.y, 0.f);
            float v10 = fmaxf(c[mt][nt][2] + bb.x, 0.f);
            float v11 = fmaxf(c[mt][nt][3] + bb.y, 0.f);
            if (r0 < M) {
                *(float2*)(Cout + (size_t)r0 * DH + cn) = make_float2(v00, v01);
                if (WBF) {
                    __nv_bfloat16 h0 = __float2bfloat16(v00);
                    __nv_bfloat16 h1 = __float2bfloat16(v01);
                    *(unsigned*)(outH + (size_t)r0 * DH + cn) =
                        (unsigned)__bfloat16_as_ushort(h0) |
                        ((unsigned)__bfloat16_as_ushort(h1) << 16);
                    *(unsigned*)(outL + (size_t)r0 * DH + cn) =
                        pack2(v00 - __bfloat162float(h0), v01 - __bfloat162float(h1));
                }
            }
            if (r1 < M) {
                *(float2*)(Cout + (size_t)r1 * DH + cn) = make_float2(v10, v11);
                if (WBF) {
                    __nv_bfloat16 h0 = __float2bfloat16(v10);
                    __nv_bfloat16 h1 = __float2bfloat16(v11);
                    *(unsigned*)(outH + (size_t)r1 * DH + cn) =
                        (unsigned)__bfloat16_as_ushort(h0) |
                        ((unsigned)__bfloat16_as_ushort(h1) << 16);
                    *(unsigned*)(outL + (size_t)r1 * DH + cn) =
                        pack2(v10 - __bfloat162float(h0), v11 - __bfloat162float(h1));
                }
            }
        }
    }
}

// ---------------- pooling: segment scan over sorted batch ----------------
#define PCH 64
__global__ void k_pool2(const int* __restrict__ batch, float* __restrict__ out, int n) {
    int i0 = blockIdx.x * PCH;
    if (i0 >= n) return;
    int i1 = min(n, i0 + PCH);
    int t = threadIdx.x;  // 256 columns
    int cur = batch[i0];
    int segStart = i0;
    float acc = 0.f;
    for (int i = i0; i < i1; ++i) {
        int b = batch[i];
        if (b != cur) {
            atomicAdd(&out[(size_t)cur * DH + t], acc);
            if (t == 0) atomicAdd(&g_gcnt[cur], (float)(i - segStart));
            acc = 0.f; cur = b; segStart = i;
        }
        acc += g_h[(size_t)i * DH + t];
    }
    atomicAdd(&out[(size_t)cur * DH + t], acc);
    if (t == 0) atomicAdd(&g_gcnt[cur], (float)(i1 - segStart));
}

__global__ void k_pool_div(float* __restrict__ out) {
    int i = blockIdx.x * blockDim.x + threadIdx.x;
    if (i < NG * DH) {
        float cnt = g_gcnt[i / DH];
        out[i] = out[i] / fmaxf(cnt, 1.f);
    }
}

// ---------------- launch ----------------
extern "C" void kernel_launch(void* const* d_in, const int* in_sizes, int n_in,
                              void* d_out, int out_size) {
    const float* x       = (const float*)d_in[0];
    const int*   ei      = (const int*)d_in[1];
    const int*   batch   = (const int*)d_in[2];
    const float* W1_rel  = (const float*)d_in[3];
    const float* W1_root = (const float*)d_in[4];
    const float* b1      = (const float*)d_in[5];
    const float* W2_rel  = (const float*)d_in[6];
    const float* W2_root = (const float*)d_in[7];
    const float* b2      = (const float*)d_in[8];
    float* out = (float*)d_out;

    const int N = in_sizes[0] / DIN;
    const int E = in_sizes[1] / 2;
    const int* src = ei;
    const int* dst = ei + E;

    const int SMEM = 3 * 15360 * (int)sizeof(__nv_bfloat16);  // 92160 B
    cudaFuncSetAttribute(k_gemm<1>, cudaFuncAttributeMaxDynamicSharedMemorySize, SMEM);
    cudaFuncSetAttribute(k_gemm<2>, cudaFuncAttributeMaxDynamicSharedMemorySize, SMEM);
    cudaFuncSetAttribute(k_gemm<3>, cudaFuncAttributeMaxDynamicSharedMemorySize, SMEM);

    {
        int n = N > NG * DH ? N : NG * DH;
        k_zero<<<(n + 255) / 256, 256>>>(out, N);
    }
    // CSR build
    k_hist<<<(E + 255) / 256, 256>>>(dst, E);
    k_scan<<<1, 1024>>>(N);
    k_fill<<<(E + 255) / 256, 256>>>(src, dst, E);

    // weight prep + x conversion (+colsum fused)
    k_prep<<<(DH * 2 * DIN + DH * 2 * DH + 255) / 256, 256>>>(W1_rel, W1_root, W2_rel, W2_root);
    k_xprep<<<512, DIN>>>(x, N);
    k_hand<<<1, DIN>>>(out);

    dim3 ggrid((N + 127) / 128, DH / 64);

    // layer 1
    k_agg_bf<DIN, 0><<<(N + 7) / 8, 256>>>(x, N);
    k_gemm<1><<<ggrid, 256, SMEM>>>(b1, N);
    // layer 2
    k_agg_bf<DH, 1><<<(N + 7) / 8, 256>>>(nullptr, N);
    k_gemm<2><<<ggrid, 256, SMEM>>>(b2, N);
    // layer 3
    k_agg_bf<DH, 1><<<(N + 7) / 8, 256>>>(nullptr, N);
    k_gemm<3><<<ggrid, 256, SMEM>>>(b2, N);

    // global mean pool
    k_pool2<<<(N + PCH - 1) / PCH, 256>>>(batch, out, N);
    k_pool_div<<<(NG * DH + 255) / 256, 256>>>(out);
}

// round 7
// speedup vs baseline: 3.2178x; 1.8332x over previous
#include <cuda_runtime.h>
#include <cuda_fp16.h>
#include <math.h>
#include <stdint.h>

#define NMAX 50000
#define EMAX 800000
#define DH   256
#define DIN  128
#define NG   64

// ---------------- device scratch ----------------
__device__ __half g_hA[(size_t)NMAX * DH];   // activations ping
__device__ __half g_hB[(size_t)NMAX * DH];   // activations pong
__device__ __half g_x16[(size_t)NMAX * DIN]; // x in fp16
__device__ __half g_agg16[(size_t)NMAX * DH];
// transposed weights fp16: Bt[n][k2], k2 = [rel | root]
__device__ __half g_Bt1[DH * 2 * DIN];
__device__ __half g_Bt2[DH * 2 * DH];

__device__ int   g_rowptr[NMAX + 1];
__device__ int   g_cnt [NMAX];
__device__ int   g_cnt2[NMAX];
__device__ int   g_col [EMAX];
__device__ float g_colsum[DIN];
__device__ float g_gcnt[NG];

// ---------------- helpers ----------------
#define MMA(c, a, b) \
    asm volatile("mma.sync.aligned.m16n8k16.row.col.f32.f16.f16.f32 " \
                 "{%0,%1,%2,%3},{%4,%5,%6,%7},{%8,%9},{%0,%1,%2,%3};" \
                 : "+f"((c)[0]), "+f"((c)[1]), "+f"((c)[2]), "+f"((c)[3]) \
                 : "r"((a)[0]), "r"((a)[1]), "r"((a)[2]), "r"((a)[3]), \
                   "r"((b)[0]), "r"((b)[1]))

__device__ __forceinline__ void ldsm4(unsigned* r, const __half* p) {
    unsigned a = (unsigned)__cvta_generic_to_shared((void*)p);
    asm volatile("ldmatrix.sync.aligned.m8n8.x4.shared.b16 {%0,%1,%2,%3}, [%4];"
                 : "=r"(r[0]), "=r"(r[1]), "=r"(r[2]), "=r"(r[3]) : "r"(a));
}
__device__ __forceinline__ void cpa16(__half* dst, const __half* src, bool pred) {
    unsigned d = (unsigned)__cvta_generic_to_shared((void*)dst);
    int sz = pred ? 16 : 0;
    asm volatile("cp.async.cg.shared.global [%0], [%1], 16, %2;"
                 :: "r"(d), "l"(src), "r"(sz));
}
#define CP_COMMIT() asm volatile("cp.async.commit_group;")

// ---------------- zero scratch + output accumulators ----------------
__global__ void k_zero(float* __restrict__ out, int n) {
    int i = blockIdx.x * blockDim.x + threadIdx.x;
    if (i < n)       { g_cnt[i] = 0; g_cnt2[i] = 0; }
    if (i < NG * DH) out[i] = 0.f;
    if (i < DIN)     g_colsum[i] = 0.f;
    if (i < NG)      g_gcnt[i] = 0.f;
}

// ---------------- CSR build ----------------
__global__ void k_hist(const int* __restrict__ dst, int E) {
    int e = blockIdx.x * blockDim.x + threadIdx.x;
    if (e < E) atomicAdd(&g_cnt[dst[e]], 1);
}

__global__ void k_scan(int n) {
    __shared__ int sh[1024];
    int t = threadIdx.x;
    int C = (n + 1023) >> 10;
    int b = t * C;
    int e = min(n, b + C);
    int s = 0;
    for (int i = b; i < e; ++i) s += g_cnt[i];
    sh[t] = s;
    __syncthreads();
    for (int off = 1; off < 1024; off <<= 1) {
        int v = (t >= off) ? sh[t - off] : 0;
        __syncthreads();
        sh[t] += v;
        __syncthreads();
    }
    int run = (t == 0) ? 0 : sh[t - 1];
    for (int i = b; i < e; ++i) { g_rowptr[i] = run; run += g_cnt[i]; }
    if (t == 1023) g_rowptr[n] = sh[1023];
}

__global__ void k_fill(const int* __restrict__ src,
                       const int* __restrict__ dst, int E) {
    int e = blockIdx.x * blockDim.x + threadIdx.x;
    if (e < E) {
        int d = dst[e];
        int pos = g_rowptr[d] + atomicAdd(&g_cnt2[d], 1);
        g_col[pos] = src[e];
    }
}

// ---------------- weight prep: transpose to fp16 ----------------
__global__ void k_prep(const float* __restrict__ W1_rel, const float* __restrict__ W1_root,
                       const float* __restrict__ W2_rel, const float* __restrict__ W2_root) {
    int i = blockIdx.x * 256 + threadIdx.x;
    const int n1 = DH * 2 * DIN;
    const int n2 = DH * 2 * DH;
    if (i < n1) {
        int n = i / (2 * DIN), k2 = i % (2 * DIN);
        float w = (k2 < DIN) ? W1_rel[(size_t)k2 * DH + n]
                             : W1_root[(size_t)(k2 - DIN) * DH + n];
        g_Bt1[i] = __float2half_rn(w);
    } else if (i < n1 + n2) {
        int j = i - n1;
        int n = j / (2 * DH), k2 = j % (2 * DH);
        float w = (k2 < DH) ? W2_rel[(size_t)k2 * DH + n]
                            : W2_root[(size_t)(k2 - DH) * DH + n];
        g_Bt2[j] = __float2half_rn(w);
    }
}

// ---------------- x prep: fp16 convert + column sums (fused) ----------------
__global__ void k_xprep(const float* __restrict__ x, int n) {
    int t = threadIdx.x;  // 128 threads = DIN channels
    float acc = 0.f;
    for (int r = blockIdx.x; r < n; r += gridDim.x) {
        float v = x[(size_t)r * DIN + t];
        acc += v;
        g_x16[(size_t)r * DIN + t] = __float2half_rn(v);
    }
    atomicAdd(&g_colsum[t], acc);
}

__global__ void k_hand(float* __restrict__ out) {
    __shared__ float sh[DIN];
    int t = threadIdx.x;
    float v = g_colsum[t];
    sh[t] = v;
    __syncthreads();
    for (int o = 64; o > 0; o >>= 1) {
        if (t < o) sh[t] += sh[t + o];
        __syncthreads();
    }
    float total = sh[0];
    out[NG * DH + t] = v / total;
    if (t == 0) out[NG * DH + DIN] = logf(total);
}

// ---------------- aggregation: warp per node, fp16 gather, f32 accumulate ----------------
// SRC: 0 = g_x16 (D=128), 1 = g_hA (D=256), 2 = g_hB (D=256)
template<int D, int SRC>
__global__ void k_agg16(int n) {
    const __half* __restrict__ h =
        (SRC == 0) ? g_x16 : (SRC == 1 ? (const __half*)g_hA : (const __half*)g_hB);
    int node = blockIdx.x * 8 + (threadIdx.x >> 5);
    int lane = threadIdx.x & 31;
    if (node >= n) return;
    int s = g_rowptr[node];
    int e = g_rowptr[node + 1];

    if (D == 256) {
        float acc[8] = {0, 0, 0, 0, 0, 0, 0, 0};
        for (int i = s; i < e; ++i) {
            int u = g_col[i];
            uint4 v = ((const uint4*)(h + (size_t)u * D))[lane];
            float2 f0 = __half22float2(*(__half2*)&v.x);
            float2 f1 = __half22float2(*(__half2*)&v.y);
            float2 f2 = __half22float2(*(__half2*)&v.z);
            float2 f3 = __half22float2(*(__half2*)&v.w);
            acc[0] += f0.x; acc[1] += f0.y; acc[2] += f1.x; acc[3] += f1.y;
            acc[4] += f2.x; acc[5] += f2.y; acc[6] += f3.x; acc[7] += f3.y;
        }
        uint4 o;
        __half2 p0 = __floats2half2_rn(acc[0], acc[1]);
        __half2 p1 = __floats2half2_rn(acc[2], acc[3]);
        __half2 p2 = __floats2half2_rn(acc[4], acc[5]);
        __half2 p3 = __floats2half2_rn(acc[6], acc[7]);
        o.x = *(unsigned*)&p0; o.y = *(unsigned*)&p1;
        o.z = *(unsigned*)&p2; o.w = *(unsigned*)&p3;
        ((uint4*)(g_agg16 + (size_t)node * D))[lane] = o;
    } else {
        float acc[4] = {0, 0, 0, 0};
        for (int i = s; i < e; ++i) {
            int u = g_col[i];
            uint2 v = ((const uint2*)(h + (size_t)u * D))[lane];
            float2 f0 = __half22float2(*(__half2*)&v.x);
            float2 f1 = __half22float2(*(__half2*)&v.y);
            acc[0] += f0.x; acc[1] += f0.y; acc[2] += f1.x; acc[3] += f1.y;
        }
        uint2 o;
        __half2 p0 = __floats2half2_rn(acc[0], acc[1]);
        __half2 p1 = __floats2half2_rn(acc[2], acc[3]);
        o.x = *(unsigned*)&p0; o.y = *(unsigned*)&p1;
        ((uint2*)(g_agg16 + (size_t)node * D))[lane] = o;
    }
}

// ---------------- pipelined fp16 tensor-core GEMM ----------------
// h_out = relu([agg16 | root] @ Bt^T + bias), single-product fp16, f32 accum.
// BM=128, BN=128, BK=32, 256 threads, warps 4Mx2N (warp tile 32x64).
// 3-stage cp.async pipeline, ldmatrix fragment loads.
// dyn smem/stage (halves): As 128x40 @0, Bs 128x40 @5120; stage stride 10240.
template<int LAYER>
__global__ void __launch_bounds__(256, 2)
k_gemm(const float* __restrict__ bias, int M) {
    constexpr int K  = (LAYER == 1) ? DIN : DH;
    constexpr int K2 = 2 * K;
    constexpr int T  = K2 / 32;

    const __half* __restrict__ root =
        (LAYER == 1) ? g_x16 : (LAYER == 2 ? (const __half*)g_hA : (const __half*)g_hB);
    const __half* __restrict__ Bt = (LAYER == 1) ? g_Bt1 : g_Bt2;
    __half* __restrict__ hout = (LAYER == 2) ? g_hB : g_hA;

    extern __shared__ __half sm[];
    __shared__ float sbias[DH];

    const int tid  = threadIdx.x;
    const int lane = tid & 31;
    const int warp = tid >> 5;
    const int wm   = warp >> 1;   // 0..3 -> M offset wm*32
    const int wn   = warp & 1;    // 0..1 -> N offset wn*64
    const int gID  = lane >> 2;
    const int tg   = lane & 3;
    const int m0   = blockIdx.x * 128;
    const int n0   = blockIdx.y * 128;

    if (tid < DH) sbias[tid] = bias[tid];

    float c[2][8][4];
#pragma unroll
    for (int mt = 0; mt < 2; ++mt)
#pragma unroll
        for (int nt = 0; nt < 8; ++nt)
#pragma unroll
            for (int q = 0; q < 4; ++q) c[mt][nt][q] = 0.f;

    auto load_stage = [&](int it, int s) {
        const bool first = (it * 32 < K);
        const __half* __restrict__ srcA = first ? g_agg16 : root;
        const int col = first ? it * 32 : it * 32 - K;
        __half* st = sm + s * 10240;
        // A: 128 rows x 32 cols = 512 chunks of 16B
#pragma unroll
        for (int i = 0; i < 2; ++i) {
            int q = tid + 256 * i;
            int r = q >> 2, cq = q & 3;
            int gr = m0 + r;
            bool p = gr < M;
            cpa16(st + r * 40 + cq * 8,
                  srcA + (size_t)(p ? gr : 0) * K + col + cq * 8, p);
        }
        // B: 128 rows x 32 cols
#pragma unroll
        for (int i = 0; i < 2; ++i) {
            int q = tid + 256 * i;
            int r = q >> 2, cq = q & 3;
            cpa16(st + 5120 + r * 40 + cq * 8,
                  Bt + (size_t)(n0 + r) * K2 + it * 32 + cq * 8, true);
        }
    };

    const int lrow = lane & 15;
    const int lk   = (lane >> 4) * 8;

    load_stage(0, 0);
    CP_COMMIT();
    load_stage(1, 1);
    CP_COMMIT();

    for (int it = 0; it < T; ++it) {
        int s = it % 3;
        if (it + 1 < T) asm volatile("cp.async.wait_group 1;");
        else            asm volatile("cp.async.wait_group 0;");
        __syncthreads();
        if (it + 2 < T) load_stage(it + 2, (it + 2) % 3);
        CP_COMMIT();

        __half* st = sm + s * 10240;
#pragma unroll
        for (int ks = 0; ks < 32; ks += 16) {
            unsigned a[2][4], b[8][2];
#pragma unroll
            for (int mt = 0; mt < 2; ++mt) {
                int rr = wm * 32 + mt * 16 + lrow;
                ldsm4(a[mt], st + rr * 40 + ks + lk);
            }
#pragma unroll
            for (int nh = 0; nh < 4; ++nh) {
                int nn = wn * 64 + nh * 16 + lrow;
                unsigned r4[4];
                ldsm4(r4, st + 5120 + nn * 40 + ks + lk);
                b[nh * 2][0] = r4[0]; b[nh * 2 + 1][0] = r4[1];
                b[nh * 2][1] = r4[2]; b[nh * 2 + 1][1] = r4[3];
            }
#pragma unroll
            for (int mt = 0; mt < 2; ++mt)
#pragma unroll
                for (int nt = 0; nt < 8; ++nt)
                    MMA(c[mt][nt], a[mt], b[nt]);
        }
        __syncthreads();
    }

    // epilogue: bias + relu, write fp16 activations
#pragma unroll
    for (int nt = 0; nt < 8; ++nt) {
        int cl = wn * 64 + nt * 8 + tg * 2;   // 0..127 within block
        int cn = n0 + cl;
        float bx = sbias[cn & (DH - 1)];
        float by = sbias[(cn + 1) & (DH - 1)];
#pragma unroll
        for (int mt = 0; mt < 2; ++mt) {
            int r0 = m0 + wm * 32 + mt * 16 + gID;
            int r1 = r0 + 8;
            if (r0 < M) {
                __half2 o = __floats2half2_rn(fmaxf(c[mt][nt][0] + bx, 0.f),
                                              fmaxf(c[mt][nt][1] + by, 0.f));
                *(__half2*)(hout + (size_t)r0 * DH + cn) = o;
            }
            if (r1 < M) {
                __half2 o = __floats2half2_rn(fmaxf(c[mt][nt][2] + bx, 0.f),
                                              fmaxf(c[mt][nt][3] + by, 0.f));
                *(__half2*)(hout + (size_t)r1 * DH + cn) = o;
            }
        }
    }
}

// ---------------- pooling: segment scan over sorted batch ----------------
#define PCH 64
__global__ void k_pool2(const int* __restrict__ batch, float* __restrict__ out, int n) {
    int i0 = blockIdx.x * PCH;
    if (i0 >= n) return;
    int i1 = min(n, i0 + PCH);
    int t = threadIdx.x;  // 256 columns
    int cur = batch[i0];
    int segStart = i0;
    float acc = 0.f;
    for (int i = i0; i < i1; ++i) {
        int b = batch[i];
        if (b != cur) {
            atomicAdd(&out[(size_t)cur * DH + t], acc);
            if (t == 0) atomicAdd(&g_gcnt[cur], (float)(i - segStart));
            acc = 0.f; cur = b; segStart = i;
        }
        acc += __half2float(g_hA[(size_t)i * DH + t]);
    }
    atomicAdd(&out[(size_t)cur * DH + t], acc);
    if (t == 0) atomicAdd(&g_gcnt[cur], (float)(i1 - segStart));
}

__global__ void k_pool_div(float* __restrict__ out) {
    int i = blockIdx.x * blockDim.x + threadIdx.x;
    if (i < NG * DH) {
        float cnt = g_gcnt[i / DH];
        out[i] = out[i] / fmaxf(cnt, 1.f);
    }
}

// ---------------- launch ----------------
extern "C" void kernel_launch(void* const* d_in, const int* in_sizes, int n_in,
                              void* d_out, int out_size) {
    const float* x       = (const float*)d_in[0];
    const int*   ei      = (const int*)d_in[1];
    const int*   batch   = (const int*)d_in[2];
    const float* W1_rel  = (const float*)d_in[3];
    const float* W1_root = (const float*)d_in[4];
    const float* b1      = (const float*)d_in[5];
    const float* W2_rel  = (const float*)d_in[6];
    const float* W2_root = (const float*)d_in[7];
    const float* b2      = (const float*)d_in[8];
    float* out = (float*)d_out;

    const int N = in_sizes[0] / DIN;
    const int E = in_sizes[1] / 2;
    const int* src = ei;
    const int* dst = ei + E;

    const int SMEM = 3 * 10240 * (int)sizeof(__half);  // 61440 B
    cudaFuncSetAttribute(k_gemm<1>, cudaFuncAttributeMaxDynamicSharedMemorySize, SMEM);
    cudaFuncSetAttribute(k_gemm<2>, cudaFuncAttributeMaxDynamicSharedMemorySize, SMEM);
    cudaFuncSetAttribute(k_gemm<3>, cudaFuncAttributeMaxDynamicSharedMemorySize, SMEM);

    {
        int n = N > NG * DH ? N : NG * DH;
        k_zero<<<(n + 255) / 256, 256>>>(out, N);
    }
    // CSR build
    k_hist<<<(E + 255) / 256, 256>>>(dst, E);
    k_scan<<<1, 1024>>>(N);
    k_fill<<<(E + 255) / 256, 256>>>(src, dst, E);

    // weight prep + x conversion (+colsum fused)
    k_prep<<<(DH * 2 * DIN + DH * 2 * DH + 255) / 256, 256>>>(W1_rel, W1_root, W2_rel, W2_root);
    k_xprep<<<512, DIN>>>(x, N);
    k_hand<<<1, DIN>>>(out);

    dim3 ggrid((N + 127) / 128, 2);

    // layer 1: agg(x) -> gemm -> hA
    k_agg16<DIN, 0><<<(N + 7) / 8, 256>>>(N);
    k_gemm<1><<<ggrid, 256, SMEM>>>(b1, N);
    // layer 2: agg(hA) -> gemm -> hB
    k_agg16<DH, 1><<<(N + 7) / 8, 256>>>(N);
    k_gemm<2><<<ggrid, 256, SMEM>>>(b2, N);
    // layer 3: agg(hB) -> gemm -> hA
    k_agg16<DH, 2><<<(N + 7) / 8, 256>>>(N);
    k_gemm<3><<<ggrid, 256, SMEM>>>(b2, N);

    // global mean pool (reads hA)
    k_pool2<<<(N + PCH - 1) / PCH, 256>>>(batch, out, N);
    k_pool_div<<<(NG * DH + 255) / 256, 256>>>(out);
}

// round 8
// speedup vs baseline: 3.3371x; 1.0371x over previous
#include <cuda_runtime.h>
#include <cuda_fp16.h>
#include <math.h>
#include <stdint.h>

#define NMAX 50000
#define EMAX 800000
#define DH   256
#define DIN  128
#define NG   64

// ---------------- device scratch ----------------
__device__ __half g_hA[(size_t)NMAX * DH];   // activations ping
__device__ __half g_hB[(size_t)NMAX * DH];   // activations pong
__device__ __half g_x16[(size_t)NMAX * DIN]; // x in fp16
__device__ __half g_agg16[(size_t)NMAX * DH];
// transposed weights fp16: Bt[n][k2], k2 = [rel | root]
__device__ __half g_Bt1[DH * 2 * DIN];
__device__ __half g_Bt2[DH * 2 * DH];

__device__ int   g_rowptr[NMAX + 1];
__device__ int   g_cnt [NMAX];
__device__ int   g_cnt2[NMAX];
__device__ int   g_col [EMAX];
__device__ float g_colsum[DIN];
__device__ float g_gcnt[NG];

// ---------------- helpers ----------------
#define MMA(c, a, b) \
    asm volatile("mma.sync.aligned.m16n8k16.row.col.f32.f16.f16.f32 " \
                 "{%0,%1,%2,%3},{%4,%5,%6,%7},{%8,%9},{%0,%1,%2,%3};" \
                 : "+f"((c)[0]), "+f"((c)[1]), "+f"((c)[2]), "+f"((c)[3]) \
                 : "r"((a)[0]), "r"((a)[1]), "r"((a)[2]), "r"((a)[3]), \
                   "r"((b)[0]), "r"((b)[1]))

__device__ __forceinline__ void ldsm4(unsigned* r, const __half* p) {
    unsigned a = (unsigned)__cvta_generic_to_shared((void*)p);
    asm volatile("ldmatrix.sync.aligned.m8n8.x4.shared.b16 {%0,%1,%2,%3}, [%4];"
                 : "=r"(r[0]), "=r"(r[1]), "=r"(r[2]), "=r"(r[3]) : "r"(a));
}
__device__ __forceinline__ void cpa16(__half* dst, const __half* src, bool pred) {
    unsigned d = (unsigned)__cvta_generic_to_shared((void*)dst);
    int sz = pred ? 16 : 0;
    asm volatile("cp.async.cg.shared.global [%0], [%1], 16, %2;"
                 :: "r"(d), "l"(src), "r"(sz));
}
#define CP_COMMIT() asm volatile("cp.async.commit_group;")

// ---------------- zero scratch + output accumulators ----------------
__global__ void k_zero(float* __restrict__ out, int n) {
    int i = blockIdx.x * blockDim.x + threadIdx.x;
    if (i < n)       { g_cnt[i] = 0; g_cnt2[i] = 0; }
    if (i < NG * DH) out[i] = 0.f;
    if (i < DIN)     g_colsum[i] = 0.f;
    if (i < NG)      g_gcnt[i] = 0.f;
}

// ---------------- CSR build ----------------
__global__ void k_hist(const int* __restrict__ dst, int E) {
    int e = blockIdx.x * blockDim.x + threadIdx.x;
    if (e < E) atomicAdd(&g_cnt[dst[e]], 1);
}

// single block, tiled warp-shuffle exclusive scan (coalesced)
__global__ void k_scan(int n) {
    __shared__ int wsum[32];
    __shared__ int s_carry;
    int t = threadIdx.x, lane = t & 31, w = t >> 5;
    if (t == 0) s_carry = 0;
    __syncthreads();
    int ntile = (n + 1023) >> 10;
    for (int tile = 0; tile < ntile; ++tile) {
        int i = (tile << 10) + t;
        int v = (i < n) ? g_cnt[i] : 0;
        // inclusive warp scan
        int x = v;
#pragma unroll
        for (int o = 1; o < 32; o <<= 1) {
            int y = __shfl_up_sync(0xFFFFFFFFu, x, o);
            if (lane >= o) x += y;
        }
        if (lane == 31) wsum[w] = x;
        __syncthreads();
        if (w == 0) {
            int s = wsum[lane];
#pragma unroll
            for (int o = 1; o < 32; o <<= 1) {
                int y = __shfl_up_sync(0xFFFFFFFFu, s, o);
                if (lane >= o) s += y;
            }
            wsum[lane] = s;
        }
        __syncthreads();
        int warpoff = (w == 0) ? 0 : wsum[w - 1];
        int excl = s_carry + warpoff + x - v;
        if (i < n) g_rowptr[i] = excl;
        int tot = wsum[31];
        __syncthreads();
        if (t == 0) s_carry += tot;
        __syncthreads();
    }
    if (t == 0) g_rowptr[n] = s_carry;
}

__global__ void k_fill(const int* __restrict__ src,
                       const int* __restrict__ dst, int E) {
    int e = blockIdx.x * blockDim.x + threadIdx.x;
    if (e < E) {
        int d = dst[e];
        int pos = g_rowptr[d] + atomicAdd(&g_cnt2[d], 1);
        g_col[pos] = src[e];
    }
}

// ---------------- weight prep: transpose to fp16 ----------------
__global__ void k_prep(const float* __restrict__ W1_rel, const float* __restrict__ W1_root,
                       const float* __restrict__ W2_rel, const float* __restrict__ W2_root) {
    int i = blockIdx.x * 256 + threadIdx.x;
    const int n1 = DH * 2 * DIN;
    const int n2 = DH * 2 * DH;
    if (i < n1) {
        int n = i / (2 * DIN), k2 = i % (2 * DIN);
        float w = (k2 < DIN) ? W1_rel[(size_t)k2 * DH + n]
                             : W1_root[(size_t)(k2 - DIN) * DH + n];
        g_Bt1[i] = __float2half_rn(w);
    } else if (i < n1 + n2) {
        int j = i - n1;
        int n = j / (2 * DH), k2 = j % (2 * DH);
        float w = (k2 < DH) ? W2_rel[(size_t)k2 * DH + n]
                            : W2_root[(size_t)(k2 - DH) * DH + n];
        g_Bt2[j] = __float2half_rn(w);
    }
}

// ---------------- x prep: fp16 convert + column sums (fused) ----------------
__global__ void k_xprep(const float* __restrict__ x, int n) {
    int t = threadIdx.x;  // 128 threads = DIN channels
    float acc = 0.f;
    for (int r = blockIdx.x; r < n; r += gridDim.x) {
        float v = x[(size_t)r * DIN + t];
        acc += v;
        g_x16[(size_t)r * DIN + t] = __float2half_rn(v);
    }
    atomicAdd(&g_colsum[t], acc);
}

__global__ void k_hand(float* __restrict__ out) {
    __shared__ float sh[DIN];
    int t = threadIdx.x;
    float v = g_colsum[t];
    sh[t] = v;
    __syncthreads();
    for (int o = 64; o > 0; o >>= 1) {
        if (t < o) sh[t] += sh[t + o];
        __syncthreads();
    }
    float total = sh[0];
    out[NG * DH + t] = v / total;
    if (t == 0) out[NG * DH + DIN] = logf(total);
}

// ---------------- aggregation: warp per node, fp16 gather, f32 accumulate ----------------
// SRC: 0 = g_x16 (D=128), 1 = g_hA (D=256), 2 = g_hB (D=256)
template<int D, int SRC>
__global__ void k_agg16(int n) {
    const __half* __restrict__ h =
        (SRC == 0) ? g_x16 : (SRC == 1 ? (const __half*)g_hA : (const __half*)g_hB);
    int node = blockIdx.x * 8 + (threadIdx.x >> 5);
    int lane = threadIdx.x & 31;
    if (node >= n) return;
    int s = g_rowptr[node];
    int e = g_rowptr[node + 1];

    if (D == 256) {
        float acc[8] = {0, 0, 0, 0, 0, 0, 0, 0};
        int i = s;
        for (; i + 2 <= e; i += 2) {
            int u = g_col[i], u2 = g_col[i + 1];
            uint4 v  = ((const uint4*)(h + (size_t)u  * D))[lane];
            uint4 v2 = ((const uint4*)(h + (size_t)u2 * D))[lane];
            float2 f0 = __half22float2(*(__half2*)&v.x);
            float2 f1 = __half22float2(*(__half2*)&v.y);
            float2 f2 = __half22float2(*(__half2*)&v.z);
            float2 f3 = __half22float2(*(__half2*)&v.w);
            float2 g0 = __half22float2(*(__half2*)&v2.x);
            float2 g1 = __half22float2(*(__half2*)&v2.y);
            float2 g2 = __half22float2(*(__half2*)&v2.z);
            float2 g3 = __half22float2(*(__half2*)&v2.w);
            acc[0] += f0.x + g0.x; acc[1] += f0.y + g0.y;
            acc[2] += f1.x + g1.x; acc[3] += f1.y + g1.y;
            acc[4] += f2.x + g2.x; acc[5] += f2.y + g2.y;
            acc[6] += f3.x + g3.x; acc[7] += f3.y + g3.y;
        }
        if (i < e) {
            int u = g_col[i];
            uint4 v = ((const uint4*)(h + (size_t)u * D))[lane];
            float2 f0 = __half22float2(*(__half2*)&v.x);
            float2 f1 = __half22float2(*(__half2*)&v.y);
            float2 f2 = __half22float2(*(__half2*)&v.z);
            float2 f3 = __half22float2(*(__half2*)&v.w);
            acc[0] += f0.x; acc[1] += f0.y; acc[2] += f1.x; acc[3] += f1.y;
            acc[4] += f2.x; acc[5] += f2.y; acc[6] += f3.x; acc[7] += f3.y;
        }
        uint4 o;
        __half2 p0 = __floats2half2_rn(acc[0], acc[1]);
        __half2 p1 = __floats2half2_rn(acc[2], acc[3]);
        __half2 p2 = __floats2half2_rn(acc[4], acc[5]);
        __half2 p3 = __floats2half2_rn(acc[6], acc[7]);
        o.x = *(unsigned*)&p0; o.y = *(unsigned*)&p1;
        o.z = *(unsigned*)&p2; o.w = *(unsigned*)&p3;
        ((uint4*)(g_agg16 + (size_t)node * D))[lane] = o;
    } else {
        float acc[4] = {0, 0, 0, 0};
        int i = s;
        for (; i + 2 <= e; i += 2) {
            int u = g_col[i], u2 = g_col[i + 1];
            uint2 v  = ((const uint2*)(h + (size_t)u  * D))[lane];
            uint2 v2 = ((const uint2*)(h + (size_t)u2 * D))[lane];
            float2 f0 = __half22float2(*(__half2*)&v.x);
            float2 f1 = __half22float2(*(__half2*)&v.y);
            float2 g0 = __half22float2(*(__half2*)&v2.x);
            float2 g1 = __half22float2(*(__half2*)&v2.y);
            acc[0] += f0.x + g0.x; acc[1] += f0.y + g0.y;
            acc[2] += f1.x + g1.x; acc[3] += f1.y + g1.y;
        }
        if (i < e) {
            int u = g_col[i];
            uint2 v = ((const uint2*)(h + (size_t)u * D))[lane];
            float2 f0 = __half22float2(*(__half2*)&v.x);
            float2 f1 = __half22float2(*(__half2*)&v.y);
            acc[0] += f0.x; acc[1] += f0.y; acc[2] += f1.x; acc[3] += f1.y;
        }
        uint2 o;
        __half2 p0 = __floats2half2_rn(acc[0], acc[1]);
        __half2 p1 = __floats2half2_rn(acc[2], acc[3]);
        o.x = *(unsigned*)&p0; o.y = *(unsigned*)&p1;
        ((uint2*)(g_agg16 + (size_t)node * D))[lane] = o;
    }
}

// ---------------- pipelined fp16 tensor-core GEMM ----------------
// h_out = relu([agg16 | root] @ Bt^T + bias), single-product fp16, f32 accum.
// BM=128, BN=128, BK=32, 256 threads, warps 4Mx2N (warp tile 32x64).
// 3-stage cp.async pipeline, ldmatrix fragment loads, one barrier per K-iter.
template<int LAYER>
__global__ void __launch_bounds__(256, 2)
k_gemm(const float* __restrict__ bias, int M) {
    constexpr int K  = (LAYER == 1) ? DIN : DH;
    constexpr int K2 = 2 * K;
    constexpr int T  = K2 / 32;

    const __half* __restrict__ root =
        (LAYER == 1) ? g_x16 : (LAYER == 2 ? (const __half*)g_hA : (const __half*)g_hB);
    const __half* __restrict__ Bt = (LAYER == 1) ? g_Bt1 : g_Bt2;
    __half* __restrict__ hout = (LAYER == 2) ? g_hB : g_hA;

    extern __shared__ __half sm[];
    __shared__ float sbias[DH];

    const int tid  = threadIdx.x;
    const int lane = tid & 31;
    const int warp = tid >> 5;
    const int wm   = warp >> 1;
    const int wn   = warp & 1;
    const int gID  = lane >> 2;
    const int tg   = lane & 3;
    const int m0   = blockIdx.x * 128;
    const int n0   = blockIdx.y * 128;

    if (tid < DH) sbias[tid] = bias[tid];

    float c[2][8][4];
#pragma unroll
    for (int mt = 0; mt < 2; ++mt)
#pragma unroll
        for (int nt = 0; nt < 8; ++nt)
#pragma unroll
            for (int q = 0; q < 4; ++q) c[mt][nt][q] = 0.f;

    auto load_stage = [&](int it, int s) {
        const bool first = (it * 32 < K);
        const __half* __restrict__ srcA = first ? g_agg16 : root;
        const int col = first ? it * 32 : it * 32 - K;
        __half* st = sm + s * 10240;
#pragma unroll
        for (int i = 0; i < 2; ++i) {
            int q = tid + 256 * i;
            int r = q >> 2, cq = q & 3;
            int gr = m0 + r;
            bool p = gr < M;
            cpa16(st + r * 40 + cq * 8,
                  srcA + (size_t)(p ? gr : 0) * K + col + cq * 8, p);
        }
#pragma unroll
        for (int i = 0; i < 2; ++i) {
            int q = tid + 256 * i;
            int r = q >> 2, cq = q & 3;
            cpa16(st + 5120 + r * 40 + cq * 8,
                  Bt + (size_t)(n0 + r) * K2 + it * 32 + cq * 8, true);
        }
    };

    const int lrow = lane & 15;
    const int lk   = (lane >> 4) * 8;

    load_stage(0, 0);
    CP_COMMIT();
    load_stage(1, 1);
    CP_COMMIT();

    for (int it = 0; it < T; ++it) {
        int s = it % 3;
        if (it + 1 < T) asm volatile("cp.async.wait_group 1;");
        else            asm volatile("cp.async.wait_group 0;");
        __syncthreads();   // stage it ready; all warps past iter it-1 (frees stage (it+2)%3)
        if (it + 2 < T) load_stage(it + 2, (it + 2) % 3);
        CP_COMMIT();

        __half* st = sm + s * 10240;
#pragma unroll
        for (int ks = 0; ks < 32; ks += 16) {
            unsigned a[2][4], b[8][2];
#pragma unroll
            for (int mt = 0; mt < 2; ++mt) {
                int rr = wm * 32 + mt * 16 + lrow;
                ldsm4(a[mt], st + rr * 40 + ks + lk);
            }
#pragma unroll
            for (int nh = 0; nh < 4; ++nh) {
                int nn = wn * 64 + nh * 16 + lrow;
                unsigned r4[4];
                ldsm4(r4, st + 5120 + nn * 40 + ks + lk);
                b[nh * 2][0] = r4[0]; b[nh * 2 + 1][0] = r4[1];
                b[nh * 2][1] = r4[2]; b[nh * 2 + 1][1] = r4[3];
            }
#pragma unroll
            for (int mt = 0; mt < 2; ++mt)
#pragma unroll
                for (int nt = 0; nt < 8; ++nt)
                    MMA(c[mt][nt], a[mt], b[nt]);
        }
    }

    // epilogue: bias + relu, write fp16 activations
#pragma unroll
    for (int nt = 0; nt < 8; ++nt) {
        int cl = wn * 64 + nt * 8 + tg * 2;
        int cn = n0 + cl;
        float bx = sbias[cn & (DH - 1)];
        float by = sbias[(cn + 1) & (DH - 1)];
#pragma unroll
        for (int mt = 0; mt < 2; ++mt) {
            int r0 = m0 + wm * 32 + mt * 16 + gID;
            int r1 = r0 + 8;
            if (r0 < M) {
                __half2 o = __floats2half2_rn(fmaxf(c[mt][nt][0] + bx, 0.f),
                                              fmaxf(c[mt][nt][1] + by, 0.f));
                *(__half2*)(hout + (size_t)r0 * DH + cn) = o;
            }
            if (r1 < M) {
                __half2 o = __floats2half2_rn(fmaxf(c[mt][nt][2] + bx, 0.f),
                                              fmaxf(c[mt][nt][3] + by, 0.f));
                *(__half2*)(hout + (size_t)r1 * DH + cn) = o;
            }
        }
    }
}

// ---------------- pooling: segment scan over sorted batch ----------------
#define PCH 64
__global__ void k_pool2(const int* __restrict__ batch, float* __restrict__ out, int n) {
    int i0 = blockIdx.x * PCH;
    if (i0 >= n) return;
    int i1 = min(n, i0 + PCH);
    int t = threadIdx.x;  // 256 columns
    int cur = batch[i0];
    int segStart = i0;
    float acc = 0.f;
    for (int i = i0; i < i1; ++i) {
        int b = batch[i];
        if (b != cur) {
            atomicAdd(&out[(size_t)cur * DH + t], acc);
            if (t == 0) atomicAdd(&g_gcnt[cur], (float)(i - segStart));
            acc = 0.f; cur = b; segStart = i;
        }
        acc += __half2float(g_hA[(size_t)i * DH + t]);
    }
    atomicAdd(&out[(size_t)cur * DH + t], acc);
    if (t == 0) atomicAdd(&g_gcnt[cur], (float)(i1 - segStart));
}

__global__ void k_pool_div(float* __restrict__ out) {
    int i = blockIdx.x * blockDim.x + threadIdx.x;
    if (i < NG * DH) {
        float cnt = g_gcnt[i / DH];
        out[i] = out[i] / fmaxf(cnt, 1.f);
    }
}

// ---------------- launch ----------------
extern "C" void kernel_launch(void* const* d_in, const int* in_sizes, int n_in,
                              void* d_out, int out_size) {
    const float* x       = (const float*)d_in[0];
    const int*   ei      = (const int*)d_in[1];
    const int*   batch   = (const int*)d_in[2];
    const float* W1_rel  = (const float*)d_in[3];
    const float* W1_root = (const float*)d_in[4];
    const float* b1      = (const float*)d_in[5];
    const float* W2_rel  = (const float*)d_in[6];
    const float* W2_root = (const float*)d_in[7];
    const float* b2      = (const float*)d_in[8];
    float* out = (float*)d_out;

    const int N = in_sizes[0] / DIN;
    const int E = in_sizes[1] / 2;
    const int* src = ei;
    const int* dst = ei + E;

    const int SMEM = 3 * 10240 * (int)sizeof(__half);  // 61440 B
    cudaFuncSetAttribute(k_gemm<1>, cudaFuncAttributeMaxDynamicSharedMemorySize, SMEM);
    cudaFuncSetAttribute(k_gemm<2>, cudaFuncAttributeMaxDynamicSharedMemorySize, SMEM);
    cudaFuncSetAttribute(k_gemm<3>, cudaFuncAttributeMaxDynamicSharedMemorySize, SMEM);

    {
        int n = N > NG * DH ? N : NG * DH;
        k_zero<<<(n + 255) / 256, 256>>>(out, N);
    }
    // CSR build
    k_hist<<<(E + 255) / 256, 256>>>(dst, E);
    k_scan<<<1, 1024>>>(N);
    k_fill<<<(E + 255) / 256, 256>>>(src, dst, E);

    // weight prep + x conversion (+colsum fused)
    k_prep<<<(DH * 2 * DIN + DH * 2 * DH + 255) / 256, 256>>>(W1_rel, W1_root, W2_rel, W2_root);
    k_xprep<<<512, DIN>>>(x, N);
    k_hand<<<1, DIN>>>(out);

    dim3 ggrid((N + 127) / 128, 2);

    // layer 1: agg(x) -> gemm -> hA
    k_agg16<DIN, 0><<<(N + 7) / 8, 256>>>(N);
    k_gemm<1><<<ggrid, 256, SMEM>>>(b1, N);
    // layer 2: agg(hA) -> gemm -> hB
    k_agg16<DH, 1><<<(N + 7) / 8, 256>>>(N);
    k_gemm<2><<<ggrid, 256, SMEM>>>(b2, N);
    // layer 3: agg(hB) -> gemm -> hA
    k_agg16<DH, 2><<<(N + 7) / 8, 256>>>(N);
    k_gemm<3><<<ggrid, 256, SMEM>>>(b2, N);

    // global mean pool (reads hA)
    k_pool2<<<(N + PCH - 1) / PCH, 256>>>(batch, out, N);
    k_pool_div<<<(NG * DH + 255) / 256, 256>>>(out);
}

// round 9
// speedup vs baseline: 3.8011x; 1.1390x over previous
#include <cuda_runtime.h>
#include <cuda_fp16.h>
#include <math.h>
#include <stdint.h>

#define NMAX 50000
#define EMAX 800000
#define DH   256
#define DIN  128
#define NG   64

// ---------------- device scratch ----------------
__device__ __half g_hA[(size_t)NMAX * DH];   // activations ping
__device__ __half g_hB[(size_t)NMAX * DH];   // activations pong
__device__ __half g_x16[(size_t)NMAX * DIN]; // x in fp16
__device__ __half g_agg16[(size_t)NMAX * DH];
// transposed weights fp16: Bt[n][k2], k2 = [rel | root]
__device__ __half g_Bt1[DH * 2 * DIN];
__device__ __half g_Bt2[DH * 2 * DH];

__device__ int   g_rowptr[NMAX + 1];
__device__ int   g_cnt [NMAX];
__device__ int   g_cnt2[NMAX];
__device__ int   g_col [EMAX];
__device__ float g_colsum[DIN];
__device__ float g_gcnt[NG];

// ---------------- helpers ----------------
#define MMA(c, a, b) \
    asm volatile("mma.sync.aligned.m16n8k16.row.col.f32.f16.f16.f32 " \
                 "{%0,%1,%2,%3},{%4,%5,%6,%7},{%8,%9},{%0,%1,%2,%3};" \
                 : "+f"((c)[0]), "+f"((c)[1]), "+f"((c)[2]), "+f"((c)[3]) \
                 : "r"((a)[0]), "r"((a)[1]), "r"((a)[2]), "r"((a)[3]), \
                   "r"((b)[0]), "r"((b)[1]))

__device__ __forceinline__ void ldsm4(unsigned* r, const __half* p) {
    unsigned a = (unsigned)__cvta_generic_to_shared((void*)p);
    asm volatile("ldmatrix.sync.aligned.m8n8.x4.shared.b16 {%0,%1,%2,%3}, [%4];"
                 : "=r"(r[0]), "=r"(r[1]), "=r"(r[2]), "=r"(r[3]) : "r"(a));
}
__device__ __forceinline__ void cpa16(__half* dst, const __half* src, bool pred) {
    unsigned d = (unsigned)__cvta_generic_to_shared((void*)dst);
    int sz = pred ? 16 : 0;
    asm volatile("cp.async.cg.shared.global [%0], [%1], 16, %2;"
                 :: "r"(d), "l"(src), "r"(sz));
}
#define CP_COMMIT() asm volatile("cp.async.commit_group;")

// ---------------- zero: cnt + output accumulators ----------------
__global__ void k_zero(float* __restrict__ out, int n) {
    int i = blockIdx.x * blockDim.x + threadIdx.x;
    if (i < n)       g_cnt[i] = 0;
    if (i < NG * DH) out[i] = 0.f;
    if (i < DIN)     g_colsum[i] = 0.f;
    if (i < NG)      g_gcnt[i] = 0.f;
}

// ---------------- fused front-end: hist | weight prep | x prep ----------------
// blocks [0,HB): edge histogram; [HB,HB+PB): weight transpose fp16;
// [HB+PB, HB+PB+XB): x fp16 convert + colsum. All independent.
__global__ void k_front(const int* __restrict__ dst, int E, int n,
                        const float* __restrict__ W1_rel, const float* __restrict__ W1_root,
                        const float* __restrict__ W2_rel, const float* __restrict__ W2_root,
                        const float* __restrict__ x,
                        int HB, int PB, int XB) {
    int bid = blockIdx.x;
    int t = threadIdx.x;
    if (bid < HB) {
        int e = bid * 256 + t;
        if (e < E) atomicAdd(&g_cnt[dst[e]], 1);
    } else if (bid < HB + PB) {
        int i = (bid - HB) * 256 + t;
        const int n1 = DH * 2 * DIN;
        const int n2 = DH * 2 * DH;
        if (i < n1) {
            int nn = i / (2 * DIN), k2 = i % (2 * DIN);
            float w = (k2 < DIN) ? W1_rel[(size_t)k2 * DH + nn]
                                 : W1_root[(size_t)(k2 - DIN) * DH + nn];
            g_Bt1[i] = __float2half_rn(w);
        } else if (i < n1 + n2) {
            int j = i - n1;
            int nn = j / (2 * DH), k2 = j % (2 * DH);
            float w = (k2 < DH) ? W2_rel[(size_t)k2 * DH + nn]
                                : W2_root[(size_t)(k2 - DH) * DH + nn];
            g_Bt2[j] = __float2half_rn(w);
        }
    } else {
        int xb = bid - HB - PB;        // 0..XB-1
        int ch = t & 127;              // channel
        int half = t >> 7;             // 0/1: two rows per iter
        float acc = 0.f;
        for (int r = xb * 2 + half; r < n; r += XB * 2) {
            float v = x[(size_t)r * DIN + ch];
            acc += v;
            g_x16[(size_t)r * DIN + ch] = __float2half_rn(v);
        }
        atomicAdd(&g_colsum[ch], acc);
    }
}

// ---------------- mid: block 0 = exclusive scan (+cnt2 init), block 1 = handcrafted ----------------
__global__ void k_mid(int n, float* __restrict__ out) {
    if (blockIdx.x == 0) {
        __shared__ int wsum[32];
        __shared__ int s_carry;
        int t = threadIdx.x, lane = t & 31, w = t >> 5;
        if (t == 0) s_carry = 0;
        __syncthreads();
        int ntile = (n + 1023) >> 10;
        for (int tile = 0; tile < ntile; ++tile) {
            int i = (tile << 10) + t;
            int v = (i < n) ? g_cnt[i] : 0;
            int x = v;
#pragma unroll
            for (int o = 1; o < 32; o <<= 1) {
                int y = __shfl_up_sync(0xFFFFFFFFu, x, o);
                if (lane >= o) x += y;
            }
            if (lane == 31) wsum[w] = x;
            __syncthreads();
            if (w == 0) {
                int s = wsum[lane];
#pragma unroll
                for (int o = 1; o < 32; o <<= 1) {
                    int y = __shfl_up_sync(0xFFFFFFFFu, s, o);
                    if (lane >= o) s += y;
                }
                wsum[lane] = s;
            }
            __syncthreads();
            int warpoff = (w == 0) ? 0 : wsum[w - 1];
            int excl = s_carry + warpoff + x - v;
            if (i < n) { g_rowptr[i] = excl; g_cnt2[i] = excl; }
            int tot = wsum[31];
            __syncthreads();
            if (t == 0) s_carry += tot;
            __syncthreads();
        }
        if (t == 0) g_rowptr[n] = s_carry;
    } else {
        __shared__ float sh[DIN];
        int t = threadIdx.x;
        float v = (t < DIN) ? g_colsum[t] : 0.f;
        if (t < DIN) sh[t] = v;
        __syncthreads();
        for (int o = 64; o > 0; o >>= 1) {
            if (t < o) sh[t] += sh[t + o];
            __syncthreads();
        }
        float total = sh[0];
        if (t < DIN) out[NG * DH + t] = v / total;
        if (t == 0) out[NG * DH + DIN] = logf(total);
    }
}

// ---------------- fill: scatter src into CSR slots (cnt2 pre-set to rowptr) ----------------
__global__ void k_fill(const int* __restrict__ src,
                       const int* __restrict__ dst, int E) {
    int e = blockIdx.x * blockDim.x + threadIdx.x;
    if (e < E) {
        int d = dst[e];
        int pos = atomicAdd(&g_cnt2[d], 1);
        g_col[pos] = src[e];
    }
}

// ---------------- aggregation: warp per node, fp16 gather, f32 accumulate ----------------
// SRC: 0 = g_x16 (D=128), 1 = g_hA (D=256), 2 = g_hB (D=256)
template<int D, int SRC>
__global__ void k_agg16(int n) {
    const __half* __restrict__ h =
        (SRC == 0) ? g_x16 : (SRC == 1 ? (const __half*)g_hA : (const __half*)g_hB);
    int node = blockIdx.x * 8 + (threadIdx.x >> 5);
    int lane = threadIdx.x & 31;
    if (node >= n) return;
    int s = g_rowptr[node];
    int e = g_rowptr[node + 1];

    if (D == 256) {
        float acc[8] = {0, 0, 0, 0, 0, 0, 0, 0};
        int i = s;
        for (; i + 4 <= e; i += 4) {
            int u0 = g_col[i], u1 = g_col[i + 1], u2 = g_col[i + 2], u3 = g_col[i + 3];
            uint4 v0 = ((const uint4*)(h + (size_t)u0 * D))[lane];
            uint4 v1 = ((const uint4*)(h + (size_t)u1 * D))[lane];
            uint4 v2 = ((const uint4*)(h + (size_t)u2 * D))[lane];
            uint4 v3 = ((const uint4*)(h + (size_t)u3 * D))[lane];
#define ACC8(v) { \
            float2 f0 = __half22float2(*(__half2*)&(v).x); \
            float2 f1 = __half22float2(*(__half2*)&(v).y); \
            float2 f2 = __half22float2(*(__half2*)&(v).z); \
            float2 f3 = __half22float2(*(__half2*)&(v).w); \
            acc[0] += f0.x; acc[1] += f0.y; acc[2] += f1.x; acc[3] += f1.y; \
            acc[4] += f2.x; acc[5] += f2.y; acc[6] += f3.x; acc[7] += f3.y; }
            ACC8(v0) ACC8(v1) ACC8(v2) ACC8(v3)
        }
        for (; i < e; ++i) {
            int u = g_col[i];
            uint4 v = ((const uint4*)(h + (size_t)u * D))[lane];
            ACC8(v)
        }
#undef ACC8
        uint4 o;
        __half2 p0 = __floats2half2_rn(acc[0], acc[1]);
        __half2 p1 = __floats2half2_rn(acc[2], acc[3]);
        __half2 p2 = __floats2half2_rn(acc[4], acc[5]);
        __half2 p3 = __floats2half2_rn(acc[6], acc[7]);
        o.x = *(unsigned*)&p0; o.y = *(unsigned*)&p1;
        o.z = *(unsigned*)&p2; o.w = *(unsigned*)&p3;
        ((uint4*)(g_agg16 + (size_t)node * D))[lane] = o;
    } else {
        float acc[4] = {0, 0, 0, 0};
        int i = s;
        for (; i + 4 <= e; i += 4) {
            int u0 = g_col[i], u1 = g_col[i + 1], u2 = g_col[i + 2], u3 = g_col[i + 3];
            uint2 v0 = ((const uint2*)(h + (size_t)u0 * D))[lane];
            uint2 v1 = ((const uint2*)(h + (size_t)u1 * D))[lane];
            uint2 v2 = ((const uint2*)(h + (size_t)u2 * D))[lane];
            uint2 v3 = ((const uint2*)(h + (size_t)u3 * D))[lane];
#define ACC4(v) { \
            float2 f0 = __half22float2(*(__half2*)&(v).x); \
            float2 f1 = __half22float2(*(__half2*)&(v).y); \
            acc[0] += f0.x; acc[1] += f0.y; acc[2] += f1.x; acc[3] += f1.y; }
            ACC4(v0) ACC4(v1) ACC4(v2) ACC4(v3)
        }
        for (; i < e; ++i) {
            int u = g_col[i];
            uint2 v = ((const uint2*)(h + (size_t)u * D))[lane];
            ACC4(v)
        }
#undef ACC4
        uint2 o;
        __half2 p0 = __floats2half2_rn(acc[0], acc[1]);
        __half2 p1 = __floats2half2_rn(acc[2], acc[3]);
        o.x = *(unsigned*)&p0; o.y = *(unsigned*)&p1;
        ((uint2*)(g_agg16 + (size_t)node * D))[lane] = o;
    }
}

// ---------------- pipelined fp16 tensor-core GEMM ----------------
// h_out = relu([agg16 | root] @ Bt^T + bias), single-product fp16, f32 accum.
// BM=128, BN=128, BK=32, 256 threads, warps 4Mx2N (warp tile 32x64).
// 3-stage cp.async pipeline, ldmatrix fragment loads, one barrier per K-iter.
template<int LAYER>
__global__ void __launch_bounds__(256, 2)
k_gemm(const float* __restrict__ bias, int M) {
    constexpr int K  = (LAYER == 1) ? DIN : DH;
    constexpr int K2 = 2 * K;
    constexpr int T  = K2 / 32;

    const __half* __restrict__ root =
        (LAYER == 1) ? g_x16 : (LAYER == 2 ? (const __half*)g_hA : (const __half*)g_hB);
    const __half* __restrict__ Bt = (LAYER == 1) ? g_Bt1 : g_Bt2;
    __half* __restrict__ hout = (LAYER == 2) ? g_hB : g_hA;

    extern __shared__ __half sm[];
    __shared__ float sbias[DH];

    const int tid  = threadIdx.x;
    const int lane = tid & 31;
    const int warp = tid >> 5;
    const int wm   = warp >> 1;
    const int wn   = warp & 1;
    const int gID  = lane >> 2;
    const int tg   = lane & 3;
    const int m0   = blockIdx.x * 128;
    const int n0   = blockIdx.y * 128;

    if (tid < DH) sbias[tid] = bias[tid];

    float c[2][8][4];
#pragma unroll
    for (int mt = 0; mt < 2; ++mt)
#pragma unroll
        for (int nt = 0; nt < 8; ++nt)
#pragma unroll
            for (int q = 0; q < 4; ++q) c[mt][nt][q] = 0.f;

    auto load_stage = [&](int it, int s) {
        const bool first = (it * 32 < K);
        const __half* __restrict__ srcA = first ? g_agg16 : root;
        const int col = first ? it * 32 : it * 32 - K;
        __half* st = sm + s * 10240;
#pragma unroll
        for (int i = 0; i < 2; ++i) {
            int q = tid + 256 * i;
            int r = q >> 2, cq = q & 3;
            int gr = m0 + r;
            bool p = gr < M;
            cpa16(st + r * 40 + cq * 8,
                  srcA + (size_t)(p ? gr : 0) * K + col + cq * 8, p);
        }
#pragma unroll
        for (int i = 0; i < 2; ++i) {
            int q = tid + 256 * i;
            int r = q >> 2, cq = q & 3;
            cpa16(st + 5120 + r * 40 + cq * 8,
                  Bt + (size_t)(n0 + r) * K2 + it * 32 + cq * 8, true);
        }
    };

    const int lrow = lane & 15;
    const int lk   = (lane >> 4) * 8;

    load_stage(0, 0);
    CP_COMMIT();
    load_stage(1, 1);
    CP_COMMIT();

    for (int it = 0; it < T; ++it) {
        int s = it % 3;
        if (it + 1 < T) asm volatile("cp.async.wait_group 1;");
        else            asm volatile("cp.async.wait_group 0;");
        __syncthreads();
        if (it + 2 < T) load_stage(it + 2, (it + 2) % 3);
        CP_COMMIT();

        __half* st = sm + s * 10240;
#pragma unroll
        for (int ks = 0; ks < 32; ks += 16) {
            unsigned a[2][4], b[8][2];
#pragma unroll
            for (int mt = 0; mt < 2; ++mt) {
                int rr = wm * 32 + mt * 16 + lrow;
                ldsm4(a[mt], st + rr * 40 + ks + lk);
            }
#pragma unroll
            for (int nh = 0; nh < 4; ++nh) {
                int nn = wn * 64 + nh * 16 + lrow;
                unsigned r4[4];
                ldsm4(r4, st + 5120 + nn * 40 + ks + lk);
                b[nh * 2][0] = r4[0]; b[nh * 2 + 1][0] = r4[1];
                b[nh * 2][1] = r4[2]; b[nh * 2 + 1][1] = r4[3];
            }
#pragma unroll
            for (int mt = 0; mt < 2; ++mt)
#pragma unroll
                for (int nt = 0; nt < 8; ++nt)
                    MMA(c[mt][nt], a[mt], b[nt]);
        }
    }

    // epilogue: bias + relu, write fp16 activations
#pragma unroll
    for (int nt = 0; nt < 8; ++nt) {
        int cl = wn * 64 + nt * 8 + tg * 2;
        int cn = n0 + cl;
        float bx = sbias[cn & (DH - 1)];
        float by = sbias[(cn + 1) & (DH - 1)];
#pragma unroll
        for (int mt = 0; mt < 2; ++mt) {
            int r0 = m0 + wm * 32 + mt * 16 + gID;
            int r1 = r0 + 8;
            if (r0 < M) {
                __half2 o = __floats2half2_rn(fmaxf(c[mt][nt][0] + bx, 0.f),
                                              fmaxf(c[mt][nt][1] + by, 0.f));
                *(__half2*)(hout + (size_t)r0 * DH + cn) = o;
            }
            if (r1 < M) {
                __half2 o = __floats2half2_rn(fmaxf(c[mt][nt][2] + bx, 0.f),
                                              fmaxf(c[mt][nt][3] + by, 0.f));
                *(__half2*)(hout + (size_t)r1 * DH + cn) = o;
            }
        }
    }
}

// ---------------- pooling: segment scan over sorted batch ----------------
#define PCH 64
__global__ void k_pool2(const int* __restrict__ batch, float* __restrict__ out, int n) {
    int i0 = blockIdx.x * PCH;
    if (i0 >= n) return;
    int i1 = min(n, i0 + PCH);
    int t = threadIdx.x;  // 256 columns
    int cur = batch[i0];
    int segStart = i0;
    float acc = 0.f;
    for (int i = i0; i < i1; ++i) {
        int b = batch[i];
        if (b != cur) {
            atomicAdd(&out[(size_t)cur * DH + t], acc);
            if (t == 0) atomicAdd(&g_gcnt[cur], (float)(i - segStart));
            acc = 0.f; cur = b; segStart = i;
        }
        acc += __half2float(g_hA[(size_t)i * DH + t]);
    }
    atomicAdd(&out[(size_t)cur * DH + t], acc);
    if (t == 0) atomicAdd(&g_gcnt[cur], (float)(i1 - segStart));
}

__global__ void k_pool_div(float* __restrict__ out) {
    int i = blockIdx.x * blockDim.x + threadIdx.x;
    if (i < NG * DH) {
        float cnt = g_gcnt[i / DH];
        out[i] = out[i] / fmaxf(cnt, 1.f);
    }
}

// ---------------- launch ----------------
extern "C" void kernel_launch(void* const* d_in, const int* in_sizes, int n_in,
                              void* d_out, int out_size) {
    const float* x       = (const float*)d_in[0];
    const int*   ei      = (const int*)d_in[1];
    const int*   batch   = (const int*)d_in[2];
    const float* W1_rel  = (const float*)d_in[3];
    const float* W1_root = (const float*)d_in[4];
    const float* b1      = (const float*)d_in[5];
    const float* W2_rel  = (const float*)d_in[6];
    const float* W2_root = (const float*)d_in[7];
    const float* b2      = (const float*)d_in[8];
    float* out = (float*)d_out;

    const int N = in_sizes[0] / DIN;
    const int E = in_sizes[1] / 2;
    const int* src = ei;
    const int* dst = ei + E;

    const int SMEM = 3 * 10240 * (int)sizeof(__half);  // 61440 B
    cudaFuncSetAttribute(k_gemm<1>, cudaFuncAttributeMaxDynamicSharedMemorySize, SMEM);
    cudaFuncSetAttribute(k_gemm<2>, cudaFuncAttributeMaxDynamicSharedMemorySize, SMEM);
    cudaFuncSetAttribute(k_gemm<3>, cudaFuncAttributeMaxDynamicSharedMemorySize, SMEM);

    {
        int n = N > NG * DH ? N : NG * DH;
        k_zero<<<(n + 255) / 256, 256>>>(out, N);
    }

    // fused front-end: histogram | weight prep | x prep (independent)
    const int HB = (E + 255) / 256;
    const int PB = (DH * 2 * DIN + DH * 2 * DH + 255) / 256;
    const int XB = 512;
    k_front<<<HB + PB + XB, 256>>>(dst, E, N, W1_rel, W1_root, W2_rel, W2_root, x,
                                   HB, PB, XB);
    // scan + handcrafted (independent blocks)
    k_mid<<<2, 1024>>>(N, out);
    k_fill<<<(E + 255) / 256, 256>>>(src, dst, E);

    dim3 ggrid((N + 127) / 128, 2);

    // layer 1: agg(x) -> gemm -> hA
    k_agg16<DIN, 0><<<(N + 7) / 8, 256>>>(N);
    k_gemm<1><<<ggrid, 256, SMEM>>>(b1, N);
    // layer 2: agg(hA) -> gemm -> hB
    k_agg16<DH, 1><<<(N + 7) / 8, 256>>>(N);
    k_gemm<2><<<ggrid, 256, SMEM>>>(b2, N);
    // layer 3: agg(hB) -> gemm -> hA
    k_agg16<DH, 2><<<(N + 7) / 8, 256>>>(N);
    k_gemm<3><<<ggrid, 256, SMEM>>>(b2, N);

    // global mean pool (reads hA)
    k_pool2<<<(N + PCH - 1) / PCH, 256>>>(batch, out, N);
    k_pool_div<<<(NG * DH + 255) / 256, 256>>>(out);
}